// round 2
// baseline (speedup 1.0000x reference)
#include <cuda_runtime.h>
#include <math.h>

#define B_ 4
#define N_ 2048
#define C_ 384
#define K_ 10
#define ROWS_ (B_*N_)      // 8192
#define EDGES_ (ROWS_*K_)  // 81920
#define LDQ 1152           // Bq | Qk | Qpart packed

// ---------------- scratch (static device globals; no allocs) ----------------
__device__ float g_V[ROWS_*C_];        // v_off
__device__ float g_A[ROWS_*C_];        // v_off @ W1_top
__device__ float g_Q3[ROWS_*LDQ];      // [Bq | Qk | Qpart]
__device__ float g_Wcat[C_*LDQ];
__device__ float g_bcat[LDQ];
__device__ int   g_knn[ROWS_*K_];
__device__ float g_shift[EDGES_*3];
__device__ int   g_i3[EDGES_*3];
__device__ float g_w3[EDGES_*3];

// flags bits for sgemm pointer selection (avoid any host-side symbol lookup)
#define F_A_GV    1   // A operand = g_V
#define F_B_WCAT  2   // B operand = g_Wcat
#define F_BIAS_BC 4   // bias = g_bcat
#define F_DST_GV  8   // C = g_V
#define F_DST_GA  16  // C = g_A
#define F_DST_GQ  32  // C = g_Q3

// ---------------- weight concat prep ----------------
// Wcat[r, 0:384]    = W1[384+r, :]              (Bq part, bias b1)
// Wcat[r, 384:768]  = Wk[r, :]                  (Qk part, bias 0)
// Wcat[r, 768:1152] = Wk[384+r, :] - Wk[r, :]   (Qpart part, bias bk)
__global__ void prep_wcat(const float* __restrict__ W1, const float* __restrict__ Wk,
                          const float* __restrict__ b1, const float* __restrict__ bk) {
    int i = blockIdx.x * 256 + threadIdx.x;
    if (i < C_ * LDQ) {
        int r = i / LDQ, c = i % LDQ;
        float v;
        if (c < C_)            v = W1[(C_ + r) * C_ + c];
        else if (c < 2 * C_)   v = Wk[r * C_ + (c - C_)];
        else                   v = Wk[(C_ + r) * C_ + (c - 2 * C_)] - Wk[r * C_ + (c - 2 * C_)];
        g_Wcat[i] = v;
    }
    if (i < LDQ) {
        float bb;
        if (i < C_)            bb = b1[i];
        else if (i < 2 * C_)   bb = 0.f;
        else                   bb = bk[i - 2 * C_];
        g_bcat[i] = bb;
    }
}

// ---------------- SGEMM: C[M,N] = A[M,K] @ B[K,N] (+bias), row-major ----------------
// BM=128, BN=64, BK=16, 256 threads, 8x4 per-thread tile.
__global__ __launch_bounds__(256) void sgemm_bias(
    const float* __restrict__ Aex, const float* __restrict__ Bex,
    const float* __restrict__ biasex, int flags,
    int M, int N, int K)
{
    const float* A    = (flags & F_A_GV)    ? g_V    : Aex;
    const float* Bm   = (flags & F_B_WCAT)  ? g_Wcat : Bex;
    const float* bias = (flags & F_BIAS_BC) ? g_bcat : biasex;
    float* Cm = (flags & F_DST_GV) ? g_V : (flags & F_DST_GA) ? g_A : g_Q3;

    __shared__ float As[16][128];
    __shared__ float Bs[16][64];
    const int tid = threadIdx.x;
    const int tx = tid & 15;       // 0..15 (N dir, x4)
    const int ty = tid >> 4;       // 0..15 (M dir, x8)
    const int rowBase = blockIdx.y * 128;
    const int colBase = blockIdx.x * 64;
    const float* Ab = A + (size_t)rowBase * K;
    const float* Bb = Bm + colBase;
    const int laRow = tid >> 2;          // 0..63
    const int laCol = (tid & 3) << 2;    // 0,4,8,12
    const int lbRow = tid >> 4;          // 0..15
    const int lbCol = (tid & 15) << 2;   // 0..60

    float acc[8][4];
#pragma unroll
    for (int i = 0; i < 8; i++)
#pragma unroll
        for (int j = 0; j < 4; j++) acc[i][j] = 0.f;

    for (int k0 = 0; k0 < K; k0 += 16) {
        float4 a0 = *(const float4*)(Ab + (size_t)laRow * K + k0 + laCol);
        float4 a1 = *(const float4*)(Ab + (size_t)(laRow + 64) * K + k0 + laCol);
        As[laCol + 0][laRow] = a0.x; As[laCol + 1][laRow] = a0.y;
        As[laCol + 2][laRow] = a0.z; As[laCol + 3][laRow] = a0.w;
        As[laCol + 0][laRow + 64] = a1.x; As[laCol + 1][laRow + 64] = a1.y;
        As[laCol + 2][laRow + 64] = a1.z; As[laCol + 3][laRow + 64] = a1.w;
        *(float4*)&Bs[lbRow][lbCol] = *(const float4*)(Bb + (size_t)(k0 + lbRow) * N + lbCol);
        __syncthreads();
#pragma unroll
        for (int kk = 0; kk < 16; kk++) {
            float4 av0 = *(const float4*)&As[kk][ty * 8];
            float4 av1 = *(const float4*)&As[kk][ty * 8 + 4];
            float4 bv4 = *(const float4*)&Bs[kk][tx * 4];
            float a[8] = {av0.x, av0.y, av0.z, av0.w, av1.x, av1.y, av1.z, av1.w};
            float b[4] = {bv4.x, bv4.y, bv4.z, bv4.w};
#pragma unroll
            for (int i = 0; i < 8; i++)
#pragma unroll
                for (int j = 0; j < 4; j++) acc[i][j] = fmaf(a[i], b[j], acc[i][j]);
        }
        __syncthreads();
    }
    float4 bb = make_float4(0.f, 0.f, 0.f, 0.f);
    if (bias) bb = *(const float4*)(bias + colBase + tx * 4);
#pragma unroll
    for (int i = 0; i < 8; i++) {
        int r = rowBase + ty * 8 + i;
        float4 o = make_float4(acc[i][0] + bb.x, acc[i][1] + bb.y,
                               acc[i][2] + bb.z, acc[i][3] + bb.w);
        *(float4*)(Cm + (size_t)r * N + colBase + tx * 4) = o;
    }
}

// ---------------- comparator helpers ----------------
__device__ __forceinline__ bool dless(float d1, int i1, float d2, int i2) {
    return (d1 < d2) || (d1 == d2 && i1 < i2);
}

// ---------------- kNN (K=10): warp per query, register top-10 + warp merge ----------------
__global__ __launch_bounds__(256) void knn_kernel(const float* __restrict__ q_pos) {
    __shared__ float4 sP[N_];
    const int qbase = blockIdx.x * 8;
    const int b = qbase >> 11;
    const float* P = q_pos + (size_t)b * N_ * 3;
    for (int i = threadIdx.x; i < N_; i += 256) {
        float x = P[i * 3 + 0], y = P[i * 3 + 1], z = P[i * 3 + 2];
        sP[i] = make_float4(x, y, z, x * x + y * y + z * z);
    }
    __syncthreads();
    const int warp = threadIdx.x >> 5, lane = threadIdx.x & 31;
    const int qi = qbase + warp;
    const float4 Q = sP[qi & (N_ - 1)];
    const float FINF = __int_as_float(0x7f800000);

    float d[K_]; int id[K_];
#pragma unroll
    for (int s = 0; s < K_; s++) { d[s] = FINF; id[s] = 0x7fffffff; }

    for (int t = 0; t < N_ / 32; t++) {
        int cand = t * 32 + lane;
        float4 Cn = sP[cand];
        float dot = Q.x * Cn.x + Q.y * Cn.y + Q.z * Cn.z;
        float dd = -2.f * dot + Q.w; dd += Cn.w;
        if (dless(dd, cand, d[K_ - 1], id[K_ - 1])) {
            d[K_ - 1] = dd; id[K_ - 1] = cand;
#pragma unroll
            for (int s = K_ - 1; s > 0; s--) {
                if (dless(d[s], id[s], d[s - 1], id[s - 1])) {
                    float td = d[s]; d[s] = d[s - 1]; d[s - 1] = td;
                    int ti = id[s]; id[s] = id[s - 1]; id[s - 1] = ti;
                }
            }
        }
    }
#pragma unroll
    for (int r = 0; r < K_; r++) {
        float vd = d[0]; int vi = id[0];
#pragma unroll
        for (int off = 16; off; off >>= 1) {
            float od = __shfl_xor_sync(0xffffffffu, vd, off);
            int   oi = __shfl_xor_sync(0xffffffffu, vi, off);
            if (dless(od, oi, vd, vi)) { vd = od; vi = oi; }
        }
        if (id[0] == vi) {  // pop winner (indices unique)
#pragma unroll
            for (int s = 0; s < K_ - 1; s++) { d[s] = d[s + 1]; id[s] = id[s + 1]; }
            d[K_ - 1] = FINF; id[K_ - 1] = 0x7fffffff;
        }
        if (lane == 0) g_knn[qi * K_ + r] = vi;
    }
}

// ---------------- per-edge MLP: h=A[nb]+Bq[n], LN, GELU, @W2, tanh, shift_pos ----------------
__global__ __launch_bounds__(256) void offset_kernel(
    const float* __restrict__ q_pos, const float* __restrict__ ln_g,
    const float* __restrict__ ln_b, const float* __restrict__ W2)
{
    const int warp = threadIdx.x >> 5, lane = threadIdx.x & 31;
    const int e = blockIdx.x * 8 + warp;
    const int b = e / (N_ * K_);
    const int rem = e - b * (N_ * K_);
    const int n = rem / K_;
    const int k = rem - n * K_;
    const int rowq = b * N_ + n;
    const int nb = g_knn[rowq * K_ + k];
    const int rownb = b * N_ + nb;

    const float* Arow = g_A + (size_t)rownb * C_;
    const float* Brow = g_Q3 + (size_t)rowq * LDQ;   // Bq at cols [0,384)

    float h[12];
    float s = 0.f;
#pragma unroll
    for (int j = 0; j < 12; j++) {
        int c = j * 32 + lane;
        h[j] = Arow[c] + Brow[c];
        s += h[j];
    }
#pragma unroll
    for (int off = 16; off; off >>= 1) s += __shfl_xor_sync(0xffffffffu, s, off);
    float mu = s * (1.f / C_);
    float v = 0.f;
#pragma unroll
    for (int j = 0; j < 12; j++) { float t = h[j] - mu; v += t * t; }
#pragma unroll
    for (int off = 16; off; off >>= 1) v += __shfl_xor_sync(0xffffffffu, v, off);
    float rstd = rsqrtf(v * (1.f / C_) + 1e-5f);

    float s0 = 0.f, s1 = 0.f, s2 = 0.f;
#pragma unroll
    for (int j = 0; j < 12; j++) {
        int c = j * 32 + lane;
        float g = (h[j] - mu) * rstd * ln_g[c] + ln_b[c];
        float y = 0.5f * g * (1.f + erff(g * 0.70710678118654752f));
        s0 = fmaf(y, W2[c * 3 + 0], s0);
        s1 = fmaf(y, W2[c * 3 + 1], s1);
        s2 = fmaf(y, W2[c * 3 + 2], s2);
    }
#pragma unroll
    for (int off = 16; off; off >>= 1) {
        s0 += __shfl_xor_sync(0xffffffffu, s0, off);
        s1 += __shfl_xor_sync(0xffffffffu, s1, off);
        s2 += __shfl_xor_sync(0xffffffffu, s2, off);
    }
    float o0 = tanhf(s0), o1 = tanhf(s1), o2 = tanhf(s2);

    // scale = (max-min over the K neighbor positions) * 0.5
    const float FINF = __int_as_float(0x7f800000);
    float mnx =  FINF, mny =  FINF, mnz =  FINF;
    float mxx = -FINF, mxy = -FINF, mxz = -FINF;
    if (lane < K_) {
        int nb2 = g_knn[rowq * K_ + lane];
        const float* pp = q_pos + ((size_t)b * N_ + nb2) * 3;
        mnx = mxx = pp[0]; mny = mxy = pp[1]; mnz = mxz = pp[2];
    }
#pragma unroll
    for (int off = 16; off; off >>= 1) {
        mnx = fminf(mnx, __shfl_xor_sync(0xffffffffu, mnx, off));
        mny = fminf(mny, __shfl_xor_sync(0xffffffffu, mny, off));
        mnz = fminf(mnz, __shfl_xor_sync(0xffffffffu, mnz, off));
        mxx = fmaxf(mxx, __shfl_xor_sync(0xffffffffu, mxx, off));
        mxy = fmaxf(mxy, __shfl_xor_sync(0xffffffffu, mxy, off));
        mxz = fmaxf(mxz, __shfl_xor_sync(0xffffffffu, mxz, off));
    }
    if (lane == 0) {
        const float* pp = q_pos + (size_t)rownb * 3;
        g_shift[e * 3 + 0] = pp[0] + o0 * ((mxx - mnx) * 0.5f);
        g_shift[e * 3 + 1] = pp[1] + o1 * ((mxy - mny) * 0.5f);
        g_shift[e * 3 + 2] = pp[2] + o2 * ((mxz - mnz) * 0.5f);
    }
}

// ---------------- three_nn: warp per shifted point, register top-3 ----------------
__global__ __launch_bounds__(256) void three_nn_kernel(const float* __restrict__ q_pos) {
    __shared__ float4 sP[N_];
    const int ebase = blockIdx.x * 8;
    const int b = ebase / (N_ * K_);
    const float* P = q_pos + (size_t)b * N_ * 3;
    for (int i = threadIdx.x; i < N_; i += 256) {
        float x = P[i * 3 + 0], y = P[i * 3 + 1], z = P[i * 3 + 2];
        sP[i] = make_float4(x, y, z, x * x + y * y + z * z);
    }
    __syncthreads();
    const int warp = threadIdx.x >> 5, lane = threadIdx.x & 31;
    const int e = ebase + warp;
    const float px = g_shift[e * 3 + 0];
    const float py = g_shift[e * 3 + 1];
    const float pz = g_shift[e * 3 + 2];
    const float s2 = px * px + py * py + pz * pz;
    const float FINF = __int_as_float(0x7f800000);

    float d[3]; int id[3];
#pragma unroll
    for (int s = 0; s < 3; s++) { d[s] = FINF; id[s] = 0x7fffffff; }

    for (int t = 0; t < N_ / 32; t++) {
        int cand = t * 32 + lane;
        float4 Cn = sP[cand];
        float dot = px * Cn.x + py * Cn.y + pz * Cn.z;
        float dd = -2.f * dot + s2; dd += Cn.w;
        if (dless(dd, cand, d[2], id[2])) {
            d[2] = dd; id[2] = cand;
            if (dless(d[2], id[2], d[1], id[1])) {
                float td = d[2]; d[2] = d[1]; d[1] = td;
                int ti = id[2]; id[2] = id[1]; id[1] = ti;
            }
            if (dless(d[1], id[1], d[0], id[0])) {
                float td = d[1]; d[1] = d[0]; d[0] = td;
                int ti = id[1]; id[1] = id[0]; id[0] = ti;
            }
        }
    }
    float bd[3]; int bi[3];
#pragma unroll
    for (int r = 0; r < 3; r++) {
        float vd = d[0]; int vi = id[0];
#pragma unroll
        for (int off = 16; off; off >>= 1) {
            float od = __shfl_xor_sync(0xffffffffu, vd, off);
            int   oi = __shfl_xor_sync(0xffffffffu, vi, off);
            if (dless(od, oi, vd, vi)) { vd = od; vi = oi; }
        }
        if (id[0] == vi) {
            d[0] = d[1]; id[0] = id[1];
            d[1] = d[2]; id[1] = id[2];
            d[2] = FINF; id[2] = 0x7fffffff;
        }
        bd[r] = vd; bi[r] = vi;
    }
    if (lane == 0) {
        float r0 = 1.f / (bd[0] + 1e-8f);
        float r1 = 1.f / (bd[1] + 1e-8f);
        float r2 = 1.f / (bd[2] + 1e-8f);
        float sm = r0 + r1 + r2;
        g_i3[e * 3 + 0] = bi[0]; g_w3[e * 3 + 0] = r0 / sm;
        g_i3[e * 3 + 1] = bi[1]; g_w3[e * 3 + 1] = r1 / sm;
        g_i3[e * 3 + 2] = bi[2]; g_w3[e * 3 + 2] = r2 / sm;
    }
}

// ---------------- final: out[b,n,c] = max_k lrelu( sum_j w_j*Qk[i3_j,c] + Qpart[n,c] ) ----
__global__ __launch_bounds__(128) void final_kernel(float* __restrict__ out) {
    const int row = blockIdx.x;          // b*N + n
    const int b = row >> 11;
    const int tid = threadIdx.x;         // 128, channels tid, tid+128, tid+256
    __shared__ int   sI[K_ * 3];
    __shared__ float sW[K_ * 3];
    const int e0 = row * K_;
    if (tid < K_ * 3) { sI[tid] = g_i3[e0 * 3 + tid]; sW[tid] = g_w3[e0 * 3 + tid]; }
    __syncthreads();

    const size_t baseB = (size_t)b * N_ * LDQ;
    const float* Qrow = g_Q3 + (size_t)row * LDQ + 768;   // Qpart
    float qp0 = Qrow[tid], qp1 = Qrow[tid + 128], qp2 = Qrow[tid + 256];
    const float NINF = __int_as_float(0xff800000);
    float m0 = NINF, m1 = NINF, m2 = NINF;

    for (int k = 0; k < K_; k++) {
        int   i0 = sI[3 * k + 0], i1 = sI[3 * k + 1], i2 = sI[3 * k + 2];
        float w0 = sW[3 * k + 0], w1 = sW[3 * k + 1], w2 = sW[3 * k + 2];
        const float* r0 = g_Q3 + baseB + (size_t)i0 * LDQ + 384;  // Qk
        const float* r1 = g_Q3 + baseB + (size_t)i1 * LDQ + 384;
        const float* r2 = g_Q3 + baseB + (size_t)i2 * LDQ + 384;
        {
            float v = qp0 + w0 * r0[tid] + w1 * r1[tid] + w2 * r2[tid];
            v = v > 0.f ? v : 0.2f * v; m0 = fmaxf(m0, v);
        }
        {
            float v = qp1 + w0 * r0[tid + 128] + w1 * r1[tid + 128] + w2 * r2[tid + 128];
            v = v > 0.f ? v : 0.2f * v; m1 = fmaxf(m1, v);
        }
        {
            float v = qp2 + w0 * r0[tid + 256] + w1 * r1[tid + 256] + w2 * r2[tid + 256];
            v = v > 0.f ? v : 0.2f * v; m2 = fmaxf(m2, v);
        }
    }
    float* orow = out + (size_t)row * C_;
    orow[tid] = m0; orow[tid + 128] = m1; orow[tid + 256] = m2;
}

// ---------------- launch ----------------
extern "C" void kernel_launch(void* const* d_in, const int* in_sizes, int n_in,
                              void* d_out, int out_size) {
    const float* q     = (const float*)d_in[0];
    const float* q_pos = (const float*)d_in[1];
    const float* Wv    = (const float*)d_in[2];
    const float* bv    = (const float*)d_in[3];
    const float* W1    = (const float*)d_in[4];
    const float* b1    = (const float*)d_in[5];
    const float* ln_g  = (const float*)d_in[6];
    const float* ln_b  = (const float*)d_in[7];
    const float* W2    = (const float*)d_in[8];
    const float* Wk    = (const float*)d_in[9];
    const float* bk    = (const float*)d_in[10];

    prep_wcat<<<(C_ * LDQ + 255) / 256, 256>>>(W1, Wk, b1, bk);
    knn_kernel<<<ROWS_ / 8, 256>>>(q_pos);
    // v_off = q @ Wv + bv -> g_V
    sgemm_bias<<<dim3(C_ / 64, ROWS_ / 128), 256>>>(q, Wv, bv, F_DST_GV, ROWS_, C_, C_);
    // A = g_V @ W1_top -> g_A
    sgemm_bias<<<dim3(C_ / 64, ROWS_ / 128), 256>>>(nullptr, W1, nullptr,
                                                    F_A_GV | F_DST_GA, ROWS_, C_, C_);
    // [Bq | Qk | Qpart] = q @ g_Wcat + g_bcat -> g_Q3
    sgemm_bias<<<dim3(LDQ / 64, ROWS_ / 128), 256>>>(q, nullptr, nullptr,
                                                     F_B_WCAT | F_BIAS_BC | F_DST_GQ,
                                                     ROWS_, LDQ, C_);
    offset_kernel<<<EDGES_ / 8, 256>>>(q_pos, ln_g, ln_b, W2);
    three_nn_kernel<<<EDGES_ / 8, 256>>>(q_pos);
    final_kernel<<<ROWS_, 128>>>((float*)d_out);
}

// round 3
// speedup vs baseline: 1.0228x; 1.0228x over previous
#include <cuda_runtime.h>
#include <math.h>

#define B_ 4
#define N_ 2048
#define C_ 384
#define K_ 10
#define ROWS_ (B_*N_)      // 8192
#define EDGES_ (ROWS_*K_)  // 81920
#define LDQ 1536           // [A | Bq | Qk | Qpart] packed per point

// ---------------- scratch (static device globals; no allocs) ----------------
__device__ float g_Q[ROWS_*LDQ];       // fused per-point table
__device__ float g_Wbig[C_*LDQ];       // [W_A | W1_bot | Wk_top | Wk_bot-Wk_top]
__device__ float g_bcat[LDQ];          // [bv@W1_top | b1 | 0 | bk]
__device__ int   g_knn[ROWS_*K_];
__device__ float g_shift[EDGES_*3];
__device__ int   g_i3[EDGES_*3];
__device__ float g_w3[EDGES_*3];

// flags for device-side pointer selection (no host symbol lookups)
#define F_B_WBIG   1   // B operand = g_Wbig
#define F_DST_WBIG 2   // C = g_Wbig (else g_Q)
#define F_BIAS     4   // bias = g_bcat

// ---------------- weight prep: cols 384..1536 of Wbig ----------------
__global__ void prep_wbig(const float* __restrict__ W1, const float* __restrict__ Wk) {
    int i = blockIdx.x * 256 + threadIdx.x;
    if (i >= C_ * (LDQ - C_)) return;
    int r = i / (LDQ - C_), c = i % (LDQ - C_);
    float v;
    if (c < C_)            v = W1[(C_ + r) * C_ + c];                       // Bq: W1 bottom
    else if (c < 2 * C_)   v = Wk[r * C_ + (c - C_)];                       // Qk: Wk top
    else                   v = Wk[(C_ + r) * C_ + (c - 2*C_)] - Wk[r * C_ + (c - 2*C_)];
    g_Wbig[r * LDQ + C_ + c] = v;
}

// ---------------- bias prep ----------------
__global__ void prep_bias(const float* __restrict__ bv, const float* __restrict__ W1,
                          const float* __restrict__ b1, const float* __restrict__ bk) {
    int i = blockIdx.x * 256 + threadIdx.x;
    if (i >= LDQ) return;
    float v;
    if (i < C_) {                 // bv @ W1_top
        float s = 0.f;
        for (int j = 0; j < C_; j++) s = fmaf(bv[j], W1[j * C_ + i], s);
        v = s;
    } else if (i < 2 * C_) v = b1[i - C_];
    else if (i < 3 * C_)   v = 0.f;
    else                   v = bk[i - 3 * C_];
    g_bcat[i] = v;
}

// ---------------- SGEMM 128x128x8 double-buffered, 8x8/thread ----------------
__global__ __launch_bounds__(256) void sgemm128(
    const float* __restrict__ Aex, const float* __restrict__ Bex,
    int flags, int M, int N, int K, int ldA, int ldB, int ldC)
{
    const float* A  = Aex;
    const float* Bm = (flags & F_B_WBIG) ? g_Wbig : Bex;
    float* Cm       = (flags & F_DST_WBIG) ? g_Wbig : g_Q;
    const bool useBias = (flags & F_BIAS) != 0;

    __shared__ float As[2][8][132];   // padded: conflict-free transposed stores
    __shared__ float Bs[2][8][128];

    const int tid = threadIdx.x;
    const int tx = tid & 15;          // n-dir
    const int ty = tid >> 4;          // m-dir
    const int rowBase = blockIdx.y * 128;
    const int colBase = blockIdx.x * 128;

    const int arow = tid >> 1, acol = (tid & 1) * 4;     // A: 2 thr/row, float4
    const int brow = tid >> 5, bcol = (tid & 31) * 4;    // B: 1 warp/row, float4

    const float* Aptr = A + (size_t)(rowBase + arow) * ldA + acol;
    const float* Bptr = Bm + (size_t)brow * ldB + colBase + bcol;

    float4 aReg = *(const float4*)Aptr;
    float4 bReg = *(const float4*)Bptr;

    float acc[8][8];
#pragma unroll
    for (int i = 0; i < 8; i++)
#pragma unroll
        for (int j = 0; j < 8; j++) acc[i][j] = 0.f;

    As[0][acol + 0][arow] = aReg.x; As[0][acol + 1][arow] = aReg.y;
    As[0][acol + 2][arow] = aReg.z; As[0][acol + 3][arow] = aReg.w;
    *(float4*)&Bs[0][brow][bcol] = bReg;
    __syncthreads();

    const int nIter = K >> 3;
    int buf = 0;
    for (int it = 0; it < nIter; it++) {
        if (it + 1 < nIter) {
            aReg = *(const float4*)(Aptr + (it + 1) * 8);
            bReg = *(const float4*)(Bptr + (size_t)(it + 1) * 8 * ldB);
        }
#pragma unroll
        for (int kk = 0; kk < 8; kk++) {
            float4 a0 = *(const float4*)&As[buf][kk][ty * 4];
            float4 a1 = *(const float4*)&As[buf][kk][64 + ty * 4];
            float4 b0 = *(const float4*)&Bs[buf][kk][tx * 4];
            float4 b1 = *(const float4*)&Bs[buf][kk][64 + tx * 4];
            float am[8] = {a0.x, a0.y, a0.z, a0.w, a1.x, a1.y, a1.z, a1.w};
            float bn[8] = {b0.x, b0.y, b0.z, b0.w, b1.x, b1.y, b1.z, b1.w};
#pragma unroll
            for (int i = 0; i < 8; i++)
#pragma unroll
                for (int j = 0; j < 8; j++)
                    acc[i][j] = fmaf(am[i], bn[j], acc[i][j]);
        }
        if (it + 1 < nIter) {
            int nb = buf ^ 1;
            As[nb][acol + 0][arow] = aReg.x; As[nb][acol + 1][arow] = aReg.y;
            As[nb][acol + 2][arow] = aReg.z; As[nb][acol + 3][arow] = aReg.w;
            *(float4*)&Bs[nb][brow][bcol] = bReg;
            __syncthreads();
            buf = nb;
        }
    }

    float4 bb0 = make_float4(0.f, 0.f, 0.f, 0.f), bb1 = bb0;
    if (useBias) {
        bb0 = *(const float4*)(g_bcat + colBase + tx * 4);
        bb1 = *(const float4*)(g_bcat + colBase + 64 + tx * 4);
    }
#pragma unroll
    for (int i = 0; i < 8; i++) {
        int r = rowBase + ((i < 4) ? (ty * 4 + i) : (64 + ty * 4 + i - 4));
        float* crow = Cm + (size_t)r * ldC + colBase;
        float4 o0 = make_float4(acc[i][0] + bb0.x, acc[i][1] + bb0.y,
                                acc[i][2] + bb0.z, acc[i][3] + bb0.w);
        float4 o1 = make_float4(acc[i][4] + bb1.x, acc[i][5] + bb1.y,
                                acc[i][6] + bb1.z, acc[i][7] + bb1.w);
        *(float4*)(crow + tx * 4) = o0;
        *(float4*)(crow + 64 + tx * 4) = o1;
    }
}

// ---------------- comparator ----------------
__device__ __forceinline__ bool dless(float d1, int i1, float d2, int i2) {
    return (d1 < d2) || (d1 == d2 && i1 < i2);
}

// ---------------- kNN (K=10): warp/query, 16 warps share position stage ----------------
__global__ __launch_bounds__(512) void knn_kernel(const float* __restrict__ q_pos) {
    __shared__ float4 sP[N_];
    const int qbase = blockIdx.x * 16;
    const int b = qbase >> 11;
    const float* P = q_pos + (size_t)b * N_ * 3;
    for (int i = threadIdx.x; i < N_; i += 512) {
        float x = P[i * 3 + 0], y = P[i * 3 + 1], z = P[i * 3 + 2];
        sP[i] = make_float4(x, y, z, x * x + y * y + z * z);
    }
    __syncthreads();
    const int warp = threadIdx.x >> 5, lane = threadIdx.x & 31;
    const int qi = qbase + warp;
    const float4 Q = sP[qi & (N_ - 1)];
    const float FINF = __int_as_float(0x7f800000);

    float d[K_]; int id[K_];
#pragma unroll
    for (int s = 0; s < K_; s++) { d[s] = FINF; id[s] = 0x7fffffff; }

    for (int t = 0; t < N_ / 32; t++) {
        int cand = t * 32 + lane;
        float4 Cn = sP[cand];
        float dot = Q.x * Cn.x + Q.y * Cn.y + Q.z * Cn.z;
        float dd = -2.f * dot + Q.w; dd += Cn.w;
        if (dless(dd, cand, d[K_ - 1], id[K_ - 1])) {
            d[K_ - 1] = dd; id[K_ - 1] = cand;
#pragma unroll
            for (int s = K_ - 1; s > 0; s--) {
                if (dless(d[s], id[s], d[s - 1], id[s - 1])) {
                    float td = d[s]; d[s] = d[s - 1]; d[s - 1] = td;
                    int ti = id[s]; id[s] = id[s - 1]; id[s - 1] = ti;
                }
            }
        }
    }
#pragma unroll
    for (int r = 0; r < K_; r++) {
        float vd = d[0]; int vi = id[0];
#pragma unroll
        for (int off = 16; off; off >>= 1) {
            float od = __shfl_xor_sync(0xffffffffu, vd, off);
            int   oi = __shfl_xor_sync(0xffffffffu, vi, off);
            if (dless(od, oi, vd, vi)) { vd = od; vi = oi; }
        }
        if (id[0] == vi) {
#pragma unroll
            for (int s = 0; s < K_ - 1; s++) { d[s] = d[s + 1]; id[s] = id[s + 1]; }
            d[K_ - 1] = FINF; id[K_ - 1] = 0x7fffffff;
        }
        if (lane == 0) g_knn[qi * K_ + r] = vi;
    }
}

// ---------------- per-edge MLP: h=A[nb]+Bq[n], LN, GELU, @W2, tanh ----------------
__global__ __launch_bounds__(256) void offset_kernel(
    const float* __restrict__ q_pos, const float* __restrict__ ln_g,
    const float* __restrict__ ln_b, const float* __restrict__ W2)
{
    const int warp = threadIdx.x >> 5, lane = threadIdx.x & 31;
    const int e = blockIdx.x * 8 + warp;
    const int b = e / (N_ * K_);
    const int rem = e - b * (N_ * K_);
    const int n = rem / K_;
    const int k = rem - n * K_;
    const int rowq = b * N_ + n;
    const int nb = g_knn[rowq * K_ + k];
    const int rownb = b * N_ + nb;

    const float* Arow = g_Q + (size_t)rownb * LDQ;         // A part at [0,384)
    const float* Brow = g_Q + (size_t)rowq * LDQ + C_;     // Bq at [384,768)

    float h[12];
    float s = 0.f;
#pragma unroll
    for (int j = 0; j < 12; j++) {
        int c = j * 32 + lane;
        h[j] = Arow[c] + Brow[c];
        s += h[j];
    }
#pragma unroll
    for (int off = 16; off; off >>= 1) s += __shfl_xor_sync(0xffffffffu, s, off);
    float mu = s * (1.f / C_);
    float v = 0.f;
#pragma unroll
    for (int j = 0; j < 12; j++) { float t = h[j] - mu; v += t * t; }
#pragma unroll
    for (int off = 16; off; off >>= 1) v += __shfl_xor_sync(0xffffffffu, v, off);
    float rstd = rsqrtf(v * (1.f / C_) + 1e-5f);

    float s0 = 0.f, s1 = 0.f, s2 = 0.f;
#pragma unroll
    for (int j = 0; j < 12; j++) {
        int c = j * 32 + lane;
        float g = (h[j] - mu) * rstd * ln_g[c] + ln_b[c];
        float y = 0.5f * g * (1.f + erff(g * 0.70710678118654752f));
        s0 = fmaf(y, W2[c * 3 + 0], s0);
        s1 = fmaf(y, W2[c * 3 + 1], s1);
        s2 = fmaf(y, W2[c * 3 + 2], s2);
    }
#pragma unroll
    for (int off = 16; off; off >>= 1) {
        s0 += __shfl_xor_sync(0xffffffffu, s0, off);
        s1 += __shfl_xor_sync(0xffffffffu, s1, off);
        s2 += __shfl_xor_sync(0xffffffffu, s2, off);
    }
    float o0 = tanhf(s0), o1 = tanhf(s1), o2 = tanhf(s2);

    const float FINF = __int_as_float(0x7f800000);
    float mnx =  FINF, mny =  FINF, mnz =  FINF;
    float mxx = -FINF, mxy = -FINF, mxz = -FINF;
    if (lane < K_) {
        int nb2 = g_knn[rowq * K_ + lane];
        const float* pp = q_pos + ((size_t)b * N_ + nb2) * 3;
        mnx = mxx = pp[0]; mny = mxy = pp[1]; mnz = mxz = pp[2];
    }
#pragma unroll
    for (int off = 16; off; off >>= 1) {
        mnx = fminf(mnx, __shfl_xor_sync(0xffffffffu, mnx, off));
        mny = fminf(mny, __shfl_xor_sync(0xffffffffu, mny, off));
        mnz = fminf(mnz, __shfl_xor_sync(0xffffffffu, mnz, off));
        mxx = fmaxf(mxx, __shfl_xor_sync(0xffffffffu, mxx, off));
        mxy = fmaxf(mxy, __shfl_xor_sync(0xffffffffu, mxy, off));
        mxz = fmaxf(mxz, __shfl_xor_sync(0xffffffffu, mxz, off));
    }
    if (lane == 0) {
        const float* pp = q_pos + (size_t)rownb * 3;
        g_shift[e * 3 + 0] = pp[0] + o0 * ((mxx - mnx) * 0.5f);
        g_shift[e * 3 + 1] = pp[1] + o1 * ((mxy - mny) * 0.5f);
        g_shift[e * 3 + 2] = pp[2] + o2 * ((mxz - mnz) * 0.5f);
    }
}

// ---------------- three_nn: warp/shifted-point, 16 warps share stage ----------------
__global__ __launch_bounds__(512) void three_nn_kernel(const float* __restrict__ q_pos) {
    __shared__ float4 sP[N_];
    const int ebase = blockIdx.x * 16;
    const int b = ebase / (N_ * K_);
    const float* P = q_pos + (size_t)b * N_ * 3;
    for (int i = threadIdx.x; i < N_; i += 512) {
        float x = P[i * 3 + 0], y = P[i * 3 + 1], z = P[i * 3 + 2];
        sP[i] = make_float4(x, y, z, x * x + y * y + z * z);
    }
    __syncthreads();
    const int warp = threadIdx.x >> 5, lane = threadIdx.x & 31;
    const int e = ebase + warp;
    const float px = g_shift[e * 3 + 0];
    const float py = g_shift[e * 3 + 1];
    const float pz = g_shift[e * 3 + 2];
    const float s2 = px * px + py * py + pz * pz;
    const float FINF = __int_as_float(0x7f800000);

    float d[3]; int id[3];
#pragma unroll
    for (int s = 0; s < 3; s++) { d[s] = FINF; id[s] = 0x7fffffff; }

    for (int t = 0; t < N_ / 32; t++) {
        int cand = t * 32 + lane;
        float4 Cn = sP[cand];
        float dot = px * Cn.x + py * Cn.y + pz * Cn.z;
        float dd = -2.f * dot + s2; dd += Cn.w;
        if (dless(dd, cand, d[2], id[2])) {
            d[2] = dd; id[2] = cand;
            if (dless(d[2], id[2], d[1], id[1])) {
                float td = d[2]; d[2] = d[1]; d[1] = td;
                int ti = id[2]; id[2] = id[1]; id[1] = ti;
            }
            if (dless(d[1], id[1], d[0], id[0])) {
                float td = d[1]; d[1] = d[0]; d[0] = td;
                int ti = id[1]; id[1] = id[0]; id[0] = ti;
            }
        }
    }
    float bd[3]; int bi[3];
#pragma unroll
    for (int r = 0; r < 3; r++) {
        float vd = d[0]; int vi = id[0];
#pragma unroll
        for (int off = 16; off; off >>= 1) {
            float od = __shfl_xor_sync(0xffffffffu, vd, off);
            int   oi = __shfl_xor_sync(0xffffffffu, vi, off);
            if (dless(od, oi, vd, vi)) { vd = od; vi = oi; }
        }
        if (id[0] == vi) {
            d[0] = d[1]; id[0] = id[1];
            d[1] = d[2]; id[1] = id[2];
            d[2] = FINF; id[2] = 0x7fffffff;
        }
        bd[r] = vd; bi[r] = vi;
    }
    if (lane == 0) {
        float r0 = 1.f / (bd[0] + 1e-8f);
        float r1 = 1.f / (bd[1] + 1e-8f);
        float r2 = 1.f / (bd[2] + 1e-8f);
        float sm = r0 + r1 + r2;
        g_i3[e * 3 + 0] = bi[0]; g_w3[e * 3 + 0] = r0 / sm;
        g_i3[e * 3 + 1] = bi[1]; g_w3[e * 3 + 1] = r1 / sm;
        g_i3[e * 3 + 2] = bi[2]; g_w3[e * 3 + 2] = r2 / sm;
    }
}

// ---------------- final: out[b,n,c] = max_k lrelu( Σ_j w_j*Qk[i3_j,c] + Qpart[n,c] ) ----
__global__ __launch_bounds__(128) void final_kernel(float* __restrict__ out) {
    const int row = blockIdx.x;
    const int b = row >> 11;
    const int tid = threadIdx.x;
    __shared__ int   sI[K_ * 3];
    __shared__ float sW[K_ * 3];
    const int e0 = row * K_;
    if (tid < K_ * 3) { sI[tid] = g_i3[e0 * 3 + tid]; sW[tid] = g_w3[e0 * 3 + tid]; }
    __syncthreads();

    const size_t baseB = (size_t)b * N_ * LDQ;
    const float* Qrow = g_Q + (size_t)row * LDQ + 3 * C_;   // Qpart
    float qp0 = Qrow[tid], qp1 = Qrow[tid + 128], qp2 = Qrow[tid + 256];
    const float NINF = __int_as_float(0xff800000);
    float m0 = NINF, m1 = NINF, m2 = NINF;

    for (int k = 0; k < K_; k++) {
        int   i0 = sI[3 * k + 0], i1 = sI[3 * k + 1], i2 = sI[3 * k + 2];
        float w0 = sW[3 * k + 0], w1 = sW[3 * k + 1], w2 = sW[3 * k + 2];
        const float* r0 = g_Q + baseB + (size_t)i0 * LDQ + 2 * C_;  // Qk
        const float* r1 = g_Q + baseB + (size_t)i1 * LDQ + 2 * C_;
        const float* r2 = g_Q + baseB + (size_t)i2 * LDQ + 2 * C_;
        {
            float v = qp0 + w0 * r0[tid] + w1 * r1[tid] + w2 * r2[tid];
            v = v > 0.f ? v : 0.2f * v; m0 = fmaxf(m0, v);
        }
        {
            float v = qp1 + w0 * r0[tid + 128] + w1 * r1[tid + 128] + w2 * r2[tid + 128];
            v = v > 0.f ? v : 0.2f * v; m1 = fmaxf(m1, v);
        }
        {
            float v = qp2 + w0 * r0[tid + 256] + w1 * r1[tid + 256] + w2 * r2[tid + 256];
            v = v > 0.f ? v : 0.2f * v; m2 = fmaxf(m2, v);
        }
    }
    float* orow = out + (size_t)row * C_;
    orow[tid] = m0; orow[tid + 128] = m1; orow[tid + 256] = m2;
}

// ---------------- launch ----------------
extern "C" void kernel_launch(void* const* d_in, const int* in_sizes, int n_in,
                              void* d_out, int out_size) {
    const float* q     = (const float*)d_in[0];
    const float* q_pos = (const float*)d_in[1];
    const float* Wv    = (const float*)d_in[2];
    const float* bv    = (const float*)d_in[3];
    const float* W1    = (const float*)d_in[4];
    const float* b1    = (const float*)d_in[5];
    const float* ln_g  = (const float*)d_in[6];
    const float* ln_b  = (const float*)d_in[7];
    const float* W2    = (const float*)d_in[8];
    const float* Wk    = (const float*)d_in[9];
    const float* bk    = (const float*)d_in[10];

    prep_wbig<<<(C_ * (LDQ - C_) + 255) / 256, 256>>>(W1, Wk);
    prep_bias<<<(LDQ + 255) / 256, 256>>>(bv, W1, b1, bk);
    // W_A = Wv @ W1_top  -> g_Wbig cols [0,384)
    sgemm128<<<dim3(C_ / 128, C_ / 128), 256>>>(Wv, W1, F_DST_WBIG,
                                                C_, C_, C_, C_, C_, LDQ);
    knn_kernel<<<ROWS_ / 16, 512>>>(q_pos);
    // g_Q = q @ g_Wbig + g_bcat   (8192 x 1536 x 384)
    sgemm128<<<dim3(LDQ / 128, ROWS_ / 128), 256>>>(q, nullptr,
                                                    F_B_WBIG | F_BIAS,
                                                    ROWS_, LDQ, C_, C_, LDQ, LDQ);
    offset_kernel<<<EDGES_ / 8, 256>>>(q_pos, ln_g, ln_b, W2);
    three_nn_kernel<<<EDGES_ / 16, 512>>>(q_pos);
    final_kernel<<<ROWS_, 128>>>((float*)d_out);
}

// round 4
// speedup vs baseline: 1.1768x; 1.1506x over previous
#include <cuda_runtime.h>
#include <math.h>

#define B_ 4
#define N_ 2048
#define C_ 384
#define K_ 10
#define ROWS_ (B_*N_)      // 8192
#define EDGES_ (ROWS_*K_)  // 81920
#define LDQ 1536           // [A | Bq | Qk | Qpart] packed per point
#define CAP_ 224           // per-warp survivor buffer

// ---------------- scratch (static device globals; no allocs) ----------------
__device__ float g_Q[ROWS_*LDQ];       // fused per-point table
__device__ float g_Wbig[C_*LDQ];       // [W_A | W1_bot | Wk_top | Wk_bot-Wk_top]
__device__ float g_bcat[LDQ];          // [bv@W1_top | b1 | 0 | bk]
__device__ int   g_knn[ROWS_*K_];
__device__ float g_shift[EDGES_*3];
__device__ int   g_i3[EDGES_*3];
__device__ float g_w3[EDGES_*3];

#define F_B_WBIG   1
#define F_DST_WBIG 2
#define F_BIAS     4

// ---------------- weight prep: cols 384..1536 of Wbig ----------------
__global__ void prep_wbig(const float* __restrict__ W1, const float* __restrict__ Wk) {
    int i = blockIdx.x * 256 + threadIdx.x;
    if (i >= C_ * (LDQ - C_)) return;
    int r = i / (LDQ - C_), c = i % (LDQ - C_);
    float v;
    if (c < C_)            v = W1[(C_ + r) * C_ + c];
    else if (c < 2 * C_)   v = Wk[r * C_ + (c - C_)];
    else                   v = Wk[(C_ + r) * C_ + (c - 2*C_)] - Wk[r * C_ + (c - 2*C_)];
    g_Wbig[r * LDQ + C_ + c] = v;
}

__global__ void prep_bias(const float* __restrict__ bv, const float* __restrict__ W1,
                          const float* __restrict__ b1, const float* __restrict__ bk) {
    int i = blockIdx.x * 256 + threadIdx.x;
    if (i >= LDQ) return;
    float v;
    if (i < C_) {
        float s = 0.f;
        for (int j = 0; j < C_; j++) s = fmaf(bv[j], W1[j * C_ + i], s);
        v = s;
    } else if (i < 2 * C_) v = b1[i - C_];
    else if (i < 3 * C_)   v = 0.f;
    else                   v = bk[i - 3 * C_];
    g_bcat[i] = v;
}

// ---------------- SGEMM 128x128x8 double-buffered, 8x8/thread ----------------
__global__ __launch_bounds__(256) void sgemm128(
    const float* __restrict__ Aex, const float* __restrict__ Bex,
    int flags, int M, int N, int K, int ldA, int ldB, int ldC)
{
    const float* A  = Aex;
    const float* Bm = (flags & F_B_WBIG) ? g_Wbig : Bex;
    float* Cm       = (flags & F_DST_WBIG) ? g_Wbig : g_Q;
    const bool useBias = (flags & F_BIAS) != 0;

    __shared__ float As[2][8][132];
    __shared__ float Bs[2][8][128];

    const int tid = threadIdx.x;
    const int tx = tid & 15;
    const int ty = tid >> 4;
    const int rowBase = blockIdx.y * 128;
    const int colBase = blockIdx.x * 128;

    const int arow = tid >> 1, acol = (tid & 1) * 4;
    const int brow = tid >> 5, bcol = (tid & 31) * 4;

    const float* Aptr = A + (size_t)(rowBase + arow) * ldA + acol;
    const float* Bptr = Bm + (size_t)brow * ldB + colBase + bcol;

    float4 aReg = *(const float4*)Aptr;
    float4 bReg = *(const float4*)Bptr;

    float acc[8][8];
#pragma unroll
    for (int i = 0; i < 8; i++)
#pragma unroll
        for (int j = 0; j < 8; j++) acc[i][j] = 0.f;

    As[0][acol + 0][arow] = aReg.x; As[0][acol + 1][arow] = aReg.y;
    As[0][acol + 2][arow] = aReg.z; As[0][acol + 3][arow] = aReg.w;
    *(float4*)&Bs[0][brow][bcol] = bReg;
    __syncthreads();

    const int nIter = K >> 3;
    int buf = 0;
    for (int it = 0; it < nIter; it++) {
        if (it + 1 < nIter) {
            aReg = *(const float4*)(Aptr + (it + 1) * 8);
            bReg = *(const float4*)(Bptr + (size_t)(it + 1) * 8 * ldB);
        }
#pragma unroll
        for (int kk = 0; kk < 8; kk++) {
            float4 a0 = *(const float4*)&As[buf][kk][ty * 4];
            float4 a1 = *(const float4*)&As[buf][kk][64 + ty * 4];
            float4 b0 = *(const float4*)&Bs[buf][kk][tx * 4];
            float4 b1 = *(const float4*)&Bs[buf][kk][64 + tx * 4];
            float am[8] = {a0.x, a0.y, a0.z, a0.w, a1.x, a1.y, a1.z, a1.w};
            float bn[8] = {b0.x, b0.y, b0.z, b0.w, b1.x, b1.y, b1.z, b1.w};
#pragma unroll
            for (int i = 0; i < 8; i++)
#pragma unroll
                for (int j = 0; j < 8; j++)
                    acc[i][j] = fmaf(am[i], bn[j], acc[i][j]);
        }
        if (it + 1 < nIter) {
            int nb = buf ^ 1;
            As[nb][acol + 0][arow] = aReg.x; As[nb][acol + 1][arow] = aReg.y;
            As[nb][acol + 2][arow] = aReg.z; As[nb][acol + 3][arow] = aReg.w;
            *(float4*)&Bs[nb][brow][bcol] = bReg;
            __syncthreads();
            buf = nb;
        }
    }

    float4 bb0 = make_float4(0.f, 0.f, 0.f, 0.f), bb1 = bb0;
    if (useBias) {
        bb0 = *(const float4*)(g_bcat + colBase + tx * 4);
        bb1 = *(const float4*)(g_bcat + colBase + 64 + tx * 4);
    }
#pragma unroll
    for (int i = 0; i < 8; i++) {
        int r = rowBase + ((i < 4) ? (ty * 4 + i) : (64 + ty * 4 + i - 4));
        float* crow = Cm + (size_t)r * ldC + colBase;
        float4 o0 = make_float4(acc[i][0] + bb0.x, acc[i][1] + bb0.y,
                                acc[i][2] + bb0.z, acc[i][3] + bb0.w);
        float4 o1 = make_float4(acc[i][4] + bb1.x, acc[i][5] + bb1.y,
                                acc[i][6] + bb1.z, acc[i][7] + bb1.w);
        *(float4*)(crow + tx * 4) = o0;
        *(float4*)(crow + 64 + tx * 4) = o1;
    }
}

// ---------------- comparator ----------------
__device__ __forceinline__ bool dless(float d1, int i1, float d2, int i2) {
    return (d1 < d2) || (d1 == d2 && i1 < i2);
}

// ascending bitonic sort of one float per lane; returns sorted value in-lane
__device__ __forceinline__ float warp_sort32(float m, int lane) {
#pragma unroll
    for (int k = 2; k <= 32; k <<= 1) {
#pragma unroll
        for (int j = k >> 1; j > 0; j >>= 1) {
            float other = __shfl_xor_sync(0xffffffffu, m, j);
            bool up = ((lane & k) == 0);
            bool lower = ((lane & j) == 0);
            float mn = fminf(m, other), mx = fmaxf(m, other);
            m = (lower == up) ? mn : mx;
        }
    }
    return m;
}

// ---------------- kNN (K=10): two-pass threshold selection ----------------
// grid 256 x 256thr; warp handles 4 queries against one staged batch tile.
__global__ __launch_bounds__(256) void knn_kernel(const float* __restrict__ q_pos) {
    __shared__ float4 sP[N_];
    __shared__ float  sBd[8][CAP_];
    __shared__ int    sBi[8][CAP_];
    const int qbase = blockIdx.x * 32;
    const int b = qbase >> 11;
    const float* P = q_pos + (size_t)b * N_ * 3;
    for (int i = threadIdx.x; i < N_; i += 256) {
        float x = P[i * 3 + 0], y = P[i * 3 + 1], z = P[i * 3 + 2];
        sP[i] = make_float4(x, y, z, x * x + y * y + z * z);
    }
    __syncthreads();
    const int w = threadIdx.x >> 5, lane = threadIdx.x & 31;
    const float FINF = __int_as_float(0x7f800000);

    for (int sub = 0; sub < 4; sub++) {
        const int qi = qbase + w * 4 + sub;
        const float4 Q = sP[qi & (N_ - 1)];

        // pass A: per-lane min
        float m = FINF;
        for (int t = 0; t < N_ / 32; t++) {
            float4 c = sP[t * 32 + lane];
            float dot = Q.x * c.x + Q.y * c.y + Q.z * c.z;
            float dd = fmaf(dot, -2.f, c.w + Q.w);
            m = fminf(m, dd);
        }
        float s = warp_sort32(m, lane);
        float T    = __shfl_sync(0xffffffffu, s, K_ - 1);
        float Tmax = __shfl_sync(0xffffffffu, s, 31);

        // pass B: compact survivors (retry with Tmax if undercount)
        int cnt = 0;
        float Tuse = T;
        for (int attempt = 0; attempt < 2; attempt++) {
            cnt = 0;
            for (int t = 0; t < N_ / 32; t++) {
                int cand = t * 32 + lane;
                float4 c = sP[cand];
                float dot = Q.x * c.x + Q.y * c.y + Q.z * c.z;
                float dd = fmaf(dot, -2.f, c.w + Q.w);
                bool p = (dd <= Tuse);
                unsigned mask = __ballot_sync(0xffffffffu, p);
                if (p) {
                    int pos = cnt + __popc(mask & ((1u << lane) - 1u));
                    if (pos < CAP_) { sBd[w][pos] = dd; sBi[w][pos] = cand; }
                }
                cnt += __popc(mask);
            }
            if (cnt >= K_) break;
            Tuse = Tmax;
        }
        int n = cnt < CAP_ ? cnt : CAP_;
        __syncwarp();

        // exact top-10 extraction with (dist, idx) tie-break
        for (int r = 0; r < K_; r++) {
            float bd = FINF; int bi = 0x7fffffff;
            for (int i = lane; i < n; i += 32) {
                float dd = sBd[w][i]; int ii = sBi[w][i];
                if (dless(dd, ii, bd, bi)) { bd = dd; bi = ii; }
            }
#pragma unroll
            for (int off = 16; off; off >>= 1) {
                float od = __shfl_xor_sync(0xffffffffu, bd, off);
                int   oi = __shfl_xor_sync(0xffffffffu, bi, off);
                if (dless(od, oi, bd, bi)) { bd = od; bi = oi; }
            }
            if (lane == 0) g_knn[qi * K_ + r] = bi;
            for (int i = lane; i < n; i += 32)
                if (sBi[w][i] == bi) sBd[w][i] = FINF;
            __syncwarp();
        }
    }
}

// ---------------- per-edge MLP: h=A[nb]+Bq[n], LN, GELU, @W2, tanh ----------------
__global__ __launch_bounds__(256) void offset_kernel(
    const float* __restrict__ q_pos, const float* __restrict__ ln_g,
    const float* __restrict__ ln_b, const float* __restrict__ W2)
{
    const int warp = threadIdx.x >> 5, lane = threadIdx.x & 31;
    const int e = blockIdx.x * 8 + warp;
    const int b = e / (N_ * K_);
    const int rem = e - b * (N_ * K_);
    const int n = rem / K_;
    const int k = rem - n * K_;
    const int rowq = b * N_ + n;
    const int nb = g_knn[rowq * K_ + k];
    const int rownb = b * N_ + nb;

    const float* Arow = g_Q + (size_t)rownb * LDQ;
    const float* Brow = g_Q + (size_t)rowq * LDQ + C_;

    float h[12];
    float s = 0.f;
#pragma unroll
    for (int j = 0; j < 12; j++) {
        int c = j * 32 + lane;
        h[j] = Arow[c] + Brow[c];
        s += h[j];
    }
#pragma unroll
    for (int off = 16; off; off >>= 1) s += __shfl_xor_sync(0xffffffffu, s, off);
    float mu = s * (1.f / C_);
    float v = 0.f;
#pragma unroll
    for (int j = 0; j < 12; j++) { float t = h[j] - mu; v += t * t; }
#pragma unroll
    for (int off = 16; off; off >>= 1) v += __shfl_xor_sync(0xffffffffu, v, off);
    float rstd = rsqrtf(v * (1.f / C_) + 1e-5f);

    float s0 = 0.f, s1 = 0.f, s2 = 0.f;
#pragma unroll
    for (int j = 0; j < 12; j++) {
        int c = j * 32 + lane;
        float g = (h[j] - mu) * rstd * ln_g[c] + ln_b[c];
        float y = 0.5f * g * (1.f + erff(g * 0.70710678118654752f));
        s0 = fmaf(y, W2[c * 3 + 0], s0);
        s1 = fmaf(y, W2[c * 3 + 1], s1);
        s2 = fmaf(y, W2[c * 3 + 2], s2);
    }
#pragma unroll
    for (int off = 16; off; off >>= 1) {
        s0 += __shfl_xor_sync(0xffffffffu, s0, off);
        s1 += __shfl_xor_sync(0xffffffffu, s1, off);
        s2 += __shfl_xor_sync(0xffffffffu, s2, off);
    }
    float o0 = tanhf(s0), o1 = tanhf(s1), o2 = tanhf(s2);

    const float FINF = __int_as_float(0x7f800000);
    float mnx =  FINF, mny =  FINF, mnz =  FINF;
    float mxx = -FINF, mxy = -FINF, mxz = -FINF;
    if (lane < K_) {
        int nb2 = g_knn[rowq * K_ + lane];
        const float* pp = q_pos + ((size_t)b * N_ + nb2) * 3;
        mnx = mxx = pp[0]; mny = mxy = pp[1]; mnz = mxz = pp[2];
    }
#pragma unroll
    for (int off = 16; off; off >>= 1) {
        mnx = fminf(mnx, __shfl_xor_sync(0xffffffffu, mnx, off));
        mny = fminf(mny, __shfl_xor_sync(0xffffffffu, mny, off));
        mnz = fminf(mnz, __shfl_xor_sync(0xffffffffu, mnz, off));
        mxx = fmaxf(mxx, __shfl_xor_sync(0xffffffffu, mxx, off));
        mxy = fmaxf(mxy, __shfl_xor_sync(0xffffffffu, mxy, off));
        mxz = fmaxf(mxz, __shfl_xor_sync(0xffffffffu, mxz, off));
    }
    if (lane == 0) {
        const float* pp = q_pos + (size_t)rownb * 3;
        g_shift[e * 3 + 0] = pp[0] + o0 * ((mxx - mnx) * 0.5f);
        g_shift[e * 3 + 1] = pp[1] + o1 * ((mxy - mny) * 0.5f);
        g_shift[e * 3 + 2] = pp[2] + o2 * ((mxz - mnz) * 0.5f);
    }
}

// ---------------- three_nn: two-pass threshold selection ----------------
// grid 1280 x 256thr; warp handles 8 edges against one staged batch tile.
__global__ __launch_bounds__(256) void three_nn_kernel(const float* __restrict__ q_pos) {
    __shared__ float4 sP[N_];
    __shared__ float  sBd[8][CAP_];
    __shared__ int    sBi[8][CAP_];
    const int ebase = blockIdx.x * 64;
    const int b = ebase / (N_ * K_);
    const float* P = q_pos + (size_t)b * N_ * 3;
    for (int i = threadIdx.x; i < N_; i += 256) {
        float x = P[i * 3 + 0], y = P[i * 3 + 1], z = P[i * 3 + 2];
        sP[i] = make_float4(x, y, z, x * x + y * y + z * z);
    }
    __syncthreads();
    const int w = threadIdx.x >> 5, lane = threadIdx.x & 31;
    const float FINF = __int_as_float(0x7f800000);

    for (int sub = 0; sub < 8; sub++) {
        const int e = ebase + w * 8 + sub;
        const float px = g_shift[e * 3 + 0];
        const float py = g_shift[e * 3 + 1];
        const float pz = g_shift[e * 3 + 2];
        const float qw = px * px + py * py + pz * pz;

        float m = FINF;
        for (int t = 0; t < N_ / 32; t++) {
            float4 c = sP[t * 32 + lane];
            float dot = px * c.x + py * c.y + pz * c.z;
            float dd = fmaf(dot, -2.f, c.w + qw);
            m = fminf(m, dd);
        }
        float s = warp_sort32(m, lane);
        float T    = __shfl_sync(0xffffffffu, s, 2);
        float Tmax = __shfl_sync(0xffffffffu, s, 31);

        int cnt = 0;
        float Tuse = T;
        for (int attempt = 0; attempt < 2; attempt++) {
            cnt = 0;
            for (int t = 0; t < N_ / 32; t++) {
                int cand = t * 32 + lane;
                float4 c = sP[cand];
                float dot = px * c.x + py * c.y + pz * c.z;
                float dd = fmaf(dot, -2.f, c.w + qw);
                bool p = (dd <= Tuse);
                unsigned mask = __ballot_sync(0xffffffffu, p);
                if (p) {
                    int pos = cnt + __popc(mask & ((1u << lane) - 1u));
                    if (pos < CAP_) { sBd[w][pos] = dd; sBi[w][pos] = cand; }
                }
                cnt += __popc(mask);
            }
            if (cnt >= 3) break;
            Tuse = Tmax;
        }
        int n = cnt < CAP_ ? cnt : CAP_;
        __syncwarp();

        float rd[3]; int ri[3];
        for (int r = 0; r < 3; r++) {
            float bd = FINF; int bi = 0x7fffffff;
            for (int i = lane; i < n; i += 32) {
                float dd = sBd[w][i]; int ii = sBi[w][i];
                if (dless(dd, ii, bd, bi)) { bd = dd; bi = ii; }
            }
#pragma unroll
            for (int off = 16; off; off >>= 1) {
                float od = __shfl_xor_sync(0xffffffffu, bd, off);
                int   oi = __shfl_xor_sync(0xffffffffu, bi, off);
                if (dless(od, oi, bd, bi)) { bd = od; bi = oi; }
            }
            rd[r] = bd; ri[r] = bi;
            for (int i = lane; i < n; i += 32)
                if (sBi[w][i] == bi) sBd[w][i] = FINF;
            __syncwarp();
        }
        if (lane == 0) {
            float r0 = 1.f / (rd[0] + 1e-8f);
            float r1 = 1.f / (rd[1] + 1e-8f);
            float r2 = 1.f / (rd[2] + 1e-8f);
            float sm = r0 + r1 + r2;
            g_i3[e * 3 + 0] = ri[0]; g_w3[e * 3 + 0] = r0 / sm;
            g_i3[e * 3 + 1] = ri[1]; g_w3[e * 3 + 1] = r1 / sm;
            g_i3[e * 3 + 2] = ri[2]; g_w3[e * 3 + 2] = r2 / sm;
        }
    }
}

// ---------------- final: out[b,n,c] = max_k lrelu( Σ_j w_j*Qk[i3_j,c] + Qpart[n,c] ) ----
__global__ __launch_bounds__(128) void final_kernel(float* __restrict__ out) {
    const int row = blockIdx.x;
    const int b = row >> 11;
    const int tid = threadIdx.x;
    __shared__ int   sI[K_ * 3];
    __shared__ float sW[K_ * 3];
    const int e0 = row * K_;
    if (tid < K_ * 3) { sI[tid] = g_i3[e0 * 3 + tid]; sW[tid] = g_w3[e0 * 3 + tid]; }
    __syncthreads();

    const size_t baseB = (size_t)b * N_ * LDQ;
    const float* Qrow = g_Q + (size_t)row * LDQ + 3 * C_;
    float qp0 = Qrow[tid], qp1 = Qrow[tid + 128], qp2 = Qrow[tid + 256];
    const float NINF = __int_as_float(0xff800000);
    float m0 = NINF, m1 = NINF, m2 = NINF;

    for (int k = 0; k < K_; k++) {
        int   i0 = sI[3 * k + 0], i1 = sI[3 * k + 1], i2 = sI[3 * k + 2];
        float w0 = sW[3 * k + 0], w1 = sW[3 * k + 1], w2 = sW[3 * k + 2];
        const float* r0 = g_Q + baseB + (size_t)i0 * LDQ + 2 * C_;
        const float* r1 = g_Q + baseB + (size_t)i1 * LDQ + 2 * C_;
        const float* r2 = g_Q + baseB + (size_t)i2 * LDQ + 2 * C_;
        {
            float v = qp0 + w0 * r0[tid] + w1 * r1[tid] + w2 * r2[tid];
            v = v > 0.f ? v : 0.2f * v; m0 = fmaxf(m0, v);
        }
        {
            float v = qp1 + w0 * r0[tid + 128] + w1 * r1[tid + 128] + w2 * r2[tid + 128];
            v = v > 0.f ? v : 0.2f * v; m1 = fmaxf(m1, v);
        }
        {
            float v = qp2 + w0 * r0[tid + 256] + w1 * r1[tid + 256] + w2 * r2[tid + 256];
            v = v > 0.f ? v : 0.2f * v; m2 = fmaxf(m2, v);
        }
    }
    float* orow = out + (size_t)row * C_;
    orow[tid] = m0; orow[tid + 128] = m1; orow[tid + 256] = m2;
}

// ---------------- launch ----------------
extern "C" void kernel_launch(void* const* d_in, const int* in_sizes, int n_in,
                              void* d_out, int out_size) {
    const float* q     = (const float*)d_in[0];
    const float* q_pos = (const float*)d_in[1];
    const float* Wv    = (const float*)d_in[2];
    const float* bv    = (const float*)d_in[3];
    const float* W1    = (const float*)d_in[4];
    const float* b1    = (const float*)d_in[5];
    const float* ln_g  = (const float*)d_in[6];
    const float* ln_b  = (const float*)d_in[7];
    const float* W2    = (const float*)d_in[8];
    const float* Wk    = (const float*)d_in[9];
    const float* bk    = (const float*)d_in[10];

    prep_wbig<<<(C_ * (LDQ - C_) + 255) / 256, 256>>>(W1, Wk);
    prep_bias<<<(LDQ + 255) / 256, 256>>>(bv, W1, b1, bk);
    // W_A = Wv @ W1_top  -> g_Wbig cols [0,384)
    sgemm128<<<dim3(C_ / 128, C_ / 128), 256>>>(Wv, W1, F_DST_WBIG,
                                                C_, C_, C_, C_, C_, LDQ);
    knn_kernel<<<ROWS_ / 32, 256>>>(q_pos);
    // g_Q = q @ g_Wbig + g_bcat   (8192 x 1536 x 384)
    sgemm128<<<dim3(LDQ / 128, ROWS_ / 128), 256>>>(q, nullptr,
                                                    F_B_WBIG | F_BIAS,
                                                    ROWS_, LDQ, C_, C_, LDQ, LDQ);
    offset_kernel<<<EDGES_ / 8, 256>>>(q_pos, ln_g, ln_b, W2);
    three_nn_kernel<<<EDGES_ / 64, 256>>>(q_pos);
    final_kernel<<<ROWS_, 128>>>((float*)d_out);
}

// round 6
// speedup vs baseline: 1.2045x; 1.0235x over previous
#include <cuda_runtime.h>
#include <math.h>

#define B_ 4
#define N_ 2048
#define C_ 384
#define K_ 10
#define ROWS_ (B_*N_)      // 8192
#define EDGES_ (ROWS_*K_)  // 81920
#define LDQ 1536           // [A | Bq | Qk | Qpart] packed per point
#define CAP_ 224           // per-warp survivor buffer (knn)

// ---------------- scratch ----------------
__device__ float g_Q[ROWS_*LDQ];
__device__ float g_Wbig[C_*LDQ];       // [W_A | W1_bot | Wk_top | Wk_bot-Wk_top]
__device__ float g_bcat[LDQ];          // [bv@W1_top | b1 | 0 | bk]
__device__ int   g_knn[ROWS_*K_];
__device__ float g_scale[ROWS_*3];     // (max-min)*0.5 over K neighbor positions
__device__ float g_shift[EDGES_*3];
__device__ int   g_i3[EDGES_*3];
__device__ float g_w3[EDGES_*3];

#define F_B_WBIG   1
#define F_DST_WBIG 2
#define F_BIAS     4

// ---------------- weight prep: cols 384..1536 of Wbig ----------------
__global__ void prep_wbig(const float* __restrict__ W1, const float* __restrict__ Wk) {
    int i = blockIdx.x * 256 + threadIdx.x;
    if (i >= C_ * (LDQ - C_)) return;
    int r = i / (LDQ - C_), c = i % (LDQ - C_);
    float v;
    if (c < C_)            v = W1[(C_ + r) * C_ + c];
    else if (c < 2 * C_)   v = Wk[r * C_ + (c - C_)];
    else                   v = Wk[(C_ + r) * C_ + (c - 2*C_)] - Wk[r * C_ + (c - 2*C_)];
    g_Wbig[r * LDQ + C_ + c] = v;
}

// bias: warp-per-output for bv@W1_top (first 48 blocks), elementwise for rest
__global__ __launch_bounds__(256) void prep_bias(
    const float* __restrict__ bv, const float* __restrict__ W1,
    const float* __restrict__ b1, const float* __restrict__ bk)
{
    if (blockIdx.x < 48) {               // 48 blocks * 8 warps = 384 outputs
        int w = threadIdx.x >> 5, lane = threadIdx.x & 31;
        int o = blockIdx.x * 8 + w;
        float s = 0.f;
        for (int t = 0; t < 12; t++) {
            int j = t * 32 + lane;
            s = fmaf(bv[j], W1[j * C_ + o], s);
        }
#pragma unroll
        for (int off = 16; off; off >>= 1) s += __shfl_xor_sync(0xffffffffu, s, off);
        if (lane == 0) g_bcat[o] = s;
    } else {
        int i = (blockIdx.x - 48) * 256 + threadIdx.x;   // 0..1151
        if (i >= LDQ - C_) return;
        float v;
        if (i < C_)            v = b1[i];
        else if (i < 2 * C_)   v = 0.f;
        else                   v = bk[i - 2 * C_];
        g_bcat[C_ + i] = v;
    }
}

// ---------------- SGEMM 128x128x8 double-buffered, 8x8/thread ----------------
__global__ __launch_bounds__(256) void sgemm128(
    const float* __restrict__ Aex, const float* __restrict__ Bex,
    int flags, int M, int N, int K, int ldA, int ldB, int ldC)
{
    const float* A  = Aex;
    const float* Bm = (flags & F_B_WBIG) ? g_Wbig : Bex;
    float* Cm       = (flags & F_DST_WBIG) ? g_Wbig : g_Q;
    const bool useBias = (flags & F_BIAS) != 0;

    __shared__ float As[2][8][132];
    __shared__ float Bs[2][8][128];

    const int tid = threadIdx.x;
    const int tx = tid & 15;
    const int ty = tid >> 4;
    const int rowBase = blockIdx.y * 128;
    const int colBase = blockIdx.x * 128;

    const int arow = tid >> 1, acol = (tid & 1) * 4;
    const int brow = tid >> 5, bcol = (tid & 31) * 4;

    const float* Aptr = A + (size_t)(rowBase + arow) * ldA + acol;
    const float* Bptr = Bm + (size_t)brow * ldB + colBase + bcol;

    float4 aReg = *(const float4*)Aptr;
    float4 bReg = *(const float4*)Bptr;

    float acc[8][8];
#pragma unroll
    for (int i = 0; i < 8; i++)
#pragma unroll
        for (int j = 0; j < 8; j++) acc[i][j] = 0.f;

    As[0][acol + 0][arow] = aReg.x; As[0][acol + 1][arow] = aReg.y;
    As[0][acol + 2][arow] = aReg.z; As[0][acol + 3][arow] = aReg.w;
    *(float4*)&Bs[0][brow][bcol] = bReg;
    __syncthreads();

    const int nIter = K >> 3;
    int buf = 0;
    for (int it = 0; it < nIter; it++) {
        if (it + 1 < nIter) {
            aReg = *(const float4*)(Aptr + (it + 1) * 8);
            bReg = *(const float4*)(Bptr + (size_t)(it + 1) * 8 * ldB);
        }
#pragma unroll
        for (int kk = 0; kk < 8; kk++) {
            float4 a0 = *(const float4*)&As[buf][kk][ty * 4];
            float4 a1 = *(const float4*)&As[buf][kk][64 + ty * 4];
            float4 b0 = *(const float4*)&Bs[buf][kk][tx * 4];
            float4 b1 = *(const float4*)&Bs[buf][kk][64 + tx * 4];
            float am[8] = {a0.x, a0.y, a0.z, a0.w, a1.x, a1.y, a1.z, a1.w};
            float bn[8] = {b0.x, b0.y, b0.z, b0.w, b1.x, b1.y, b1.z, b1.w};
#pragma unroll
            for (int i = 0; i < 8; i++)
#pragma unroll
                for (int j = 0; j < 8; j++)
                    acc[i][j] = fmaf(am[i], bn[j], acc[i][j]);
        }
        if (it + 1 < nIter) {
            int nb = buf ^ 1;
            As[nb][acol + 0][arow] = aReg.x; As[nb][acol + 1][arow] = aReg.y;
            As[nb][acol + 2][arow] = aReg.z; As[nb][acol + 3][arow] = aReg.w;
            *(float4*)&Bs[nb][brow][bcol] = bReg;
            __syncthreads();
            buf = nb;
        }
    }

    float4 bb0 = make_float4(0.f, 0.f, 0.f, 0.f), bb1 = bb0;
    if (useBias) {
        bb0 = *(const float4*)(g_bcat + colBase + tx * 4);
        bb1 = *(const float4*)(g_bcat + colBase + 64 + tx * 4);
    }
#pragma unroll
    for (int i = 0; i < 8; i++) {
        int r = rowBase + ((i < 4) ? (ty * 4 + i) : (64 + ty * 4 + i - 4));
        float* crow = Cm + (size_t)r * ldC + colBase;
        float4 o0 = make_float4(acc[i][0] + bb0.x, acc[i][1] + bb0.y,
                                acc[i][2] + bb0.z, acc[i][3] + bb0.w);
        float4 o1 = make_float4(acc[i][4] + bb1.x, acc[i][5] + bb1.y,
                                acc[i][6] + bb1.z, acc[i][7] + bb1.w);
        *(float4*)(crow + tx * 4) = o0;
        *(float4*)(crow + 64 + tx * 4) = o1;
    }
}

// ---------------- comparator ----------------
__device__ __forceinline__ bool dless(float d1, int i1, float d2, int i2) {
    return (d1 < d2) || (d1 == d2 && i1 < i2);
}

__device__ __forceinline__ float warp_sort32(float m, int lane) {
#pragma unroll
    for (int k = 2; k <= 32; k <<= 1) {
#pragma unroll
        for (int j = k >> 1; j > 0; j >>= 1) {
            float other = __shfl_xor_sync(0xffffffffu, m, j);
            bool up = ((lane & k) == 0);
            bool lower = ((lane & j) == 0);
            float mn = fminf(m, other), mx = fmaxf(m, other);
            m = (lower == up) ? mn : mx;
        }
    }
    return m;
}

// ---------------- kNN (K=10): 1 query/warp, two-pass threshold; also emits scale ----
__global__ __launch_bounds__(256) void knn_kernel(const float* __restrict__ q_pos) {
    __shared__ float4 sP[N_];
    __shared__ float  sBd[8][CAP_];
    __shared__ int    sBi[8][CAP_];
    const int qbase = blockIdx.x * 8;
    const int b = qbase >> 11;
    const float* P = q_pos + (size_t)b * N_ * 3;
    for (int i = threadIdx.x; i < N_; i += 256) {
        float x = P[i * 3 + 0], y = P[i * 3 + 1], z = P[i * 3 + 2];
        sP[i] = make_float4(x, y, z, x * x + y * y + z * z);
    }
    __syncthreads();
    const int w = threadIdx.x >> 5, lane = threadIdx.x & 31;
    const float FINF = __int_as_float(0x7f800000);

    const int qi = qbase + w;
    const float4 Q = sP[qi & (N_ - 1)];

    // pass A: per-lane min
    float m = FINF;
    for (int t = 0; t < N_ / 32; t++) {
        float4 c = sP[t * 32 + lane];
        float dot = Q.x * c.x + Q.y * c.y + Q.z * c.z;
        float dd = fmaf(dot, -2.f, c.w + Q.w);
        m = fminf(m, dd);
    }
    float s = warp_sort32(m, lane);
    float T    = __shfl_sync(0xffffffffu, s, K_ - 1);
    float Tmax = __shfl_sync(0xffffffffu, s, 31);

    // pass B: compact survivors
    int cnt = 0;
    float Tuse = T;
    for (int attempt = 0; attempt < 2; attempt++) {
        cnt = 0;
        for (int t = 0; t < N_ / 32; t++) {
            int cand = t * 32 + lane;
            float4 c = sP[cand];
            float dot = Q.x * c.x + Q.y * c.y + Q.z * c.z;
            float dd = fmaf(dot, -2.f, c.w + Q.w);
            bool p = (dd <= Tuse);
            unsigned mask = __ballot_sync(0xffffffffu, p);
            if (p) {
                int pos = cnt + __popc(mask & ((1u << lane) - 1u));
                if (pos < CAP_) { sBd[w][pos] = dd; sBi[w][pos] = cand; }
            }
            cnt += __popc(mask);
        }
        if (cnt >= K_) break;
        Tuse = Tmax;
    }
    int n = cnt < CAP_ ? cnt : CAP_;
    __syncwarp();

    // extraction + running min/max of winner positions
    float mnx = FINF, mny = FINF, mnz = FINF;
    float mxx = -FINF, mxy = -FINF, mxz = -FINF;
    for (int r = 0; r < K_; r++) {
        float bd = FINF; int bi = 0x7fffffff;
        for (int i = lane; i < n; i += 32) {
            float dd = sBd[w][i]; int ii = sBi[w][i];
            if (dless(dd, ii, bd, bi)) { bd = dd; bi = ii; }
        }
#pragma unroll
        for (int off = 16; off; off >>= 1) {
            float od = __shfl_xor_sync(0xffffffffu, bd, off);
            int   oi = __shfl_xor_sync(0xffffffffu, bi, off);
            if (dless(od, oi, bd, bi)) { bd = od; bi = oi; }
        }
        if (lane == 0) g_knn[qi * K_ + r] = bi;
        float4 wp = sP[bi];
        mnx = fminf(mnx, wp.x); mxx = fmaxf(mxx, wp.x);
        mny = fminf(mny, wp.y); mxy = fmaxf(mxy, wp.y);
        mnz = fminf(mnz, wp.z); mxz = fmaxf(mxz, wp.z);
        for (int i = lane; i < n; i += 32)
            if (sBi[w][i] == bi) sBd[w][i] = FINF;
        __syncwarp();
    }
    if (lane == 0) {
        g_scale[qi * 3 + 0] = (mxx - mnx) * 0.5f;
        g_scale[qi * 3 + 1] = (mxy - mny) * 0.5f;
        g_scale[qi * 3 + 2] = (mxz - mnz) * 0.5f;
    }
}

// ---------------- per-point MLP: warp per point, loops K edges ----------------
__global__ __launch_bounds__(256) void offset_kernel(
    const float* __restrict__ q_pos, const float* __restrict__ ln_g,
    const float* __restrict__ ln_b, const float* __restrict__ W2)
{
    const int w = threadIdx.x >> 5, lane = threadIdx.x & 31;
    const int p = blockIdx.x * 8 + w;            // point row [0,8192)
    const int b = p >> 11;
    const int c0 = lane * 12;                    // 12 contiguous channels per lane

    // per-point constants in registers
    float4 bq[3], lg[3], lb[3], w2f[9];
    const float* Bq = g_Q + (size_t)p * LDQ + C_ + c0;
#pragma unroll
    for (int t = 0; t < 3; t++) {
        bq[t] = *(const float4*)(Bq + t * 4);
        lg[t] = *(const float4*)(ln_g + c0 + t * 4);
        lb[t] = *(const float4*)(ln_b + c0 + t * 4);
    }
#pragma unroll
    for (int t = 0; t < 9; t++) w2f[t] = *(const float4*)(W2 + c0 * 3 + t * 4);
    const float* w2s = (const float*)w2f;
    const float* bqs = (const float*)bq;
    const float* lgs = (const float*)lg;
    const float* lbs = (const float*)lb;

    const float sx = g_scale[p * 3 + 0];
    const float sy = g_scale[p * 3 + 1];
    const float sz = g_scale[p * 3 + 2];

    for (int k = 0; k < K_; k++) {
        const int nb = g_knn[p * K_ + k];
        const int rownb = b * N_ + nb;
        const float* Arow = g_Q + (size_t)rownb * LDQ + c0;

        float h[12];
        float4 a0 = *(const float4*)(Arow);
        float4 a1 = *(const float4*)(Arow + 4);
        float4 a2 = *(const float4*)(Arow + 8);
        h[0] = a0.x + bqs[0]; h[1] = a0.y + bqs[1]; h[2] = a0.z + bqs[2]; h[3] = a0.w + bqs[3];
        h[4] = a1.x + bqs[4]; h[5] = a1.y + bqs[5]; h[6] = a1.z + bqs[6]; h[7] = a1.w + bqs[7];
        h[8] = a2.x + bqs[8]; h[9] = a2.y + bqs[9]; h[10]= a2.z + bqs[10];h[11]= a2.w + bqs[11];

        float s = 0.f;
#pragma unroll
        for (int j = 0; j < 12; j++) s += h[j];
#pragma unroll
        for (int off = 16; off; off >>= 1) s += __shfl_xor_sync(0xffffffffu, s, off);
        float mu = s * (1.f / C_);
        float v = 0.f;
#pragma unroll
        for (int j = 0; j < 12; j++) { float t = h[j] - mu; v += t * t; }
#pragma unroll
        for (int off = 16; off; off >>= 1) v += __shfl_xor_sync(0xffffffffu, v, off);
        float rstd = rsqrtf(v * (1.f / C_) + 1e-5f);

        float s0 = 0.f, s1 = 0.f, s2 = 0.f;
#pragma unroll
        for (int j = 0; j < 12; j++) {
            float g = (h[j] - mu) * rstd * lgs[j] + lbs[j];
            float y = 0.5f * g * (1.f + erff(g * 0.70710678118654752f));
            s0 = fmaf(y, w2s[j * 3 + 0], s0);
            s1 = fmaf(y, w2s[j * 3 + 1], s1);
            s2 = fmaf(y, w2s[j * 3 + 2], s2);
        }
#pragma unroll
        for (int off = 16; off; off >>= 1) {
            s0 += __shfl_xor_sync(0xffffffffu, s0, off);
            s1 += __shfl_xor_sync(0xffffffffu, s1, off);
            s2 += __shfl_xor_sync(0xffffffffu, s2, off);
        }
        if (lane == 0) {
            const int e = p * K_ + k;
            const float* pp = q_pos + (size_t)rownb * 3;
            g_shift[e * 3 + 0] = fmaf(tanhf(s0), sx, pp[0]);
            g_shift[e * 3 + 1] = fmaf(tanhf(s1), sy, pp[1]);
            g_shift[e * 3 + 2] = fmaf(tanhf(s2), sz, pp[2]);
        }
    }
}

// ---------------- three_nn: single-pass register top-3, warp per edge ----------------
__global__ __launch_bounds__(256) void three_nn_kernel(const float* __restrict__ q_pos) {
    __shared__ float4 sP[N_];
    const int ebase = blockIdx.x * 64;
    const int b = ebase / (N_ * K_);
    const float* P = q_pos + (size_t)b * N_ * 3;
    for (int i = threadIdx.x; i < N_; i += 256) {
        float x = P[i * 3 + 0], y = P[i * 3 + 1], z = P[i * 3 + 2];
        sP[i] = make_float4(x, y, z, x * x + y * y + z * z);
    }
    __syncthreads();
    const int w = threadIdx.x >> 5, lane = threadIdx.x & 31;
    const float FINF = __int_as_float(0x7f800000);

    for (int sub = 0; sub < 8; sub++) {
        const int e = ebase + w * 8 + sub;
        const float px = g_shift[e * 3 + 0];
        const float py = g_shift[e * 3 + 1];
        const float pz = g_shift[e * 3 + 2];
        const float qw = px * px + py * py + pz * pz;

        float d0 = FINF, d1 = FINF, d2 = FINF;
        int   i0 = 0x7fffffff, i1 = 0x7fffffff, i2 = 0x7fffffff;
        for (int t = 0; t < N_ / 32; t++) {
            int cand = t * 32 + lane;
            float4 c = sP[cand];
            float dot = px * c.x + py * c.y + pz * c.z;
            float dd = fmaf(dot, -2.f, c.w + qw);
            if (dless(dd, cand, d2, i2)) {
                d2 = dd; i2 = cand;
                if (dless(d2, i2, d1, i1)) {
                    float td = d1; d1 = d2; d2 = td;
                    int ti = i1; i1 = i2; i2 = ti;
                    if (dless(d1, i1, d0, i0)) {
                        td = d0; d0 = d1; d1 = td;
                        ti = i0; i0 = i1; i1 = ti;
                    }
                }
            }
        }
        // 3 rounds of warp argmin with pop
        float rd[3]; int ri[3];
#pragma unroll
        for (int r = 0; r < 3; r++) {
            float bd = d0; int bi = i0;
#pragma unroll
            for (int off = 16; off; off >>= 1) {
                float od = __shfl_xor_sync(0xffffffffu, bd, off);
                int   oi = __shfl_xor_sync(0xffffffffu, bi, off);
                if (dless(od, oi, bd, bi)) { bd = od; bi = oi; }
            }
            rd[r] = bd; ri[r] = bi;
            if (i0 == bi) { d0 = d1; i0 = i1; d1 = d2; i1 = i2; d2 = FINF; i2 = 0x7fffffff; }
        }
        if (lane == 0) {
            float r0 = 1.f / (rd[0] + 1e-8f);
            float r1 = 1.f / (rd[1] + 1e-8f);
            float r2 = 1.f / (rd[2] + 1e-8f);
            float sm = r0 + r1 + r2;
            g_i3[e * 3 + 0] = ri[0]; g_w3[e * 3 + 0] = r0 / sm;
            g_i3[e * 3 + 1] = ri[1]; g_w3[e * 3 + 1] = r1 / sm;
            g_i3[e * 3 + 2] = ri[2]; g_w3[e * 3 + 2] = r2 / sm;
        }
    }
}

// ---------------- final: 96 threads, float4 ----------------
__global__ __launch_bounds__(96) void final_kernel(float* __restrict__ out) {
    const int row = blockIdx.x;
    const int b = row >> 11;
    const int tid = threadIdx.x;          // 96 threads, 4 channels each
    __shared__ int   sI[K_ * 3];
    __shared__ float sW[K_ * 3];
    const int e0 = row * K_;
    if (tid < K_ * 3) { sI[tid] = g_i3[e0 * 3 + tid]; sW[tid] = g_w3[e0 * 3 + tid]; }
    __syncthreads();

    const size_t baseB = (size_t)b * N_ * LDQ;
    float4 qp = *(const float4*)(g_Q + (size_t)row * LDQ + 3 * C_ + tid * 4);
    const float NINF = __int_as_float(0xff800000);
    float4 mx = make_float4(NINF, NINF, NINF, NINF);

    for (int k = 0; k < K_; k++) {
        int   a0 = sI[3 * k + 0], a1 = sI[3 * k + 1], a2 = sI[3 * k + 2];
        float w0 = sW[3 * k + 0], w1 = sW[3 * k + 1], w2 = sW[3 * k + 2];
        float4 r0 = *(const float4*)(g_Q + baseB + (size_t)a0 * LDQ + 2 * C_ + tid * 4);
        float4 r1 = *(const float4*)(g_Q + baseB + (size_t)a1 * LDQ + 2 * C_ + tid * 4);
        float4 r2 = *(const float4*)(g_Q + baseB + (size_t)a2 * LDQ + 2 * C_ + tid * 4);
        float v0 = qp.x + w0 * r0.x + w1 * r1.x + w2 * r2.x;
        float v1 = qp.y + w0 * r0.y + w1 * r1.y + w2 * r2.y;
        float v2 = qp.z + w0 * r0.z + w1 * r1.z + w2 * r2.z;
        float v3 = qp.w + w0 * r0.w + w1 * r1.w + w2 * r2.w;
        v0 = v0 > 0.f ? v0 : 0.2f * v0;
        v1 = v1 > 0.f ? v1 : 0.2f * v1;
        v2 = v2 > 0.f ? v2 : 0.2f * v2;
        v3 = v3 > 0.f ? v3 : 0.2f * v3;
        mx.x = fmaxf(mx.x, v0); mx.y = fmaxf(mx.y, v1);
        mx.z = fmaxf(mx.z, v2); mx.w = fmaxf(mx.w, v3);
    }
    *(float4*)(out + (size_t)row * C_ + tid * 4) = mx;
}

// ---------------- launch ----------------
extern "C" void kernel_launch(void* const* d_in, const int* in_sizes, int n_in,
                              void* d_out, int out_size) {
    const float* q     = (const float*)d_in[0];
    const float* q_pos = (const float*)d_in[1];
    const float* Wv    = (const float*)d_in[2];
    const float* bv    = (const float*)d_in[3];
    const float* W1    = (const float*)d_in[4];
    const float* b1    = (const float*)d_in[5];
    const float* ln_g  = (const float*)d_in[6];
    const float* ln_b  = (const float*)d_in[7];
    const float* W2    = (const float*)d_in[8];
    const float* Wk    = (const float*)d_in[9];
    const float* bk    = (const float*)d_in[10];

    prep_wbig<<<(C_ * (LDQ - C_) + 255) / 256, 256>>>(W1, Wk);
    prep_bias<<<48 + (LDQ - C_ + 255) / 256, 256>>>(bv, W1, b1, bk);
    // W_A = Wv @ W1_top  -> g_Wbig cols [0,384)
    sgemm128<<<dim3(C_ / 128, C_ / 128), 256>>>(Wv, W1, F_DST_WBIG,
                                                C_, C_, C_, C_, C_, LDQ);
    knn_kernel<<<ROWS_ / 8, 256>>>(q_pos);
    // g_Q = q @ g_Wbig + g_bcat   (8192 x 1536 x 384)
    sgemm128<<<dim3(LDQ / 128, ROWS_ / 128), 256>>>(q, nullptr,
                                                    F_B_WBIG | F_BIAS,
                                                    ROWS_, LDQ, C_, C_, LDQ, LDQ);
    offset_kernel<<<ROWS_ / 8, 256>>>(q_pos, ln_g, ln_b, W2);
    three_nn_kernel<<<EDGES_ / 64, 256>>>(q_pos);
    final_kernel<<<ROWS_, 96>>>((float*)d_out);
}

// round 9
// speedup vs baseline: 1.4259x; 1.1839x over previous
#include <cuda_runtime.h>
#include <cuda_bf16.h>
#include <math.h>

#define B_ 4
#define N_ 2048
#define C_ 384
#define K_ 10
#define ROWS_ (B_*N_)      // 8192
#define EDGES_ (ROWS_*K_)  // 81920
#define LDQ 1536           // [A | Bq | Qk | Qpart] packed per point
#define CAP_ 224

// ---------------- scratch ----------------
__device__ float g_Q[ROWS_*LDQ];
__device__ float g_Wbig[C_*LDQ];            // fp32 [k][n]
__device__ float g_bcat[LDQ];
__device__ __nv_bfloat16 g_qhi[ROWS_*C_];   // q split, [M,K]
__device__ __nv_bfloat16 g_qlo[ROWS_*C_];
__device__ __nv_bfloat16 g_wbhi[LDQ*C_];    // Wbig^T split, [N,K]
__device__ __nv_bfloat16 g_wblo[LDQ*C_];
__device__ int   g_knn[ROWS_*K_];
__device__ float g_scale[ROWS_*3];
__device__ float g_shift[EDGES_*3];
__device__ int   g_i3[EDGES_*3];
__device__ float g_w3[EDGES_*3];

#define F_DST_WBIG 2

// ---------------- weight prep: cols 384..1536 of Wbig (fp32, k-major) ----------------
__global__ void prep_wbig(const float* __restrict__ W1, const float* __restrict__ Wk) {
    int i = blockIdx.x * 256 + threadIdx.x;
    if (i >= C_ * (LDQ - C_)) return;
    int r = i / (LDQ - C_), c = i % (LDQ - C_);
    float v;
    if (c < C_)            v = W1[(C_ + r) * C_ + c];
    else if (c < 2 * C_)   v = Wk[r * C_ + (c - C_)];
    else                   v = Wk[(C_ + r) * C_ + (c - 2*C_)] - Wk[r * C_ + (c - 2*C_)];
    g_Wbig[r * LDQ + C_ + c] = v;
}

__global__ __launch_bounds__(256) void prep_bias(
    const float* __restrict__ bv, const float* __restrict__ W1,
    const float* __restrict__ b1, const float* __restrict__ bk)
{
    if (blockIdx.x < 48) {
        int w = threadIdx.x >> 5, lane = threadIdx.x & 31;
        int o = blockIdx.x * 8 + w;
        float s = 0.f;
        for (int t = 0; t < 12; t++) {
            int j = t * 32 + lane;
            s = fmaf(bv[j], W1[j * C_ + o], s);
        }
#pragma unroll
        for (int off = 16; off; off >>= 1) s += __shfl_xor_sync(0xffffffffu, s, off);
        if (lane == 0) g_bcat[o] = s;
    } else {
        int i = (blockIdx.x - 48) * 256 + threadIdx.x;
        if (i >= LDQ - C_) return;
        float v;
        if (i < C_)            v = b1[i];
        else if (i < 2 * C_)   v = 0.f;
        else                   v = bk[i - 2 * C_];
        g_bcat[C_ + i] = v;
    }
}

// ---------------- split conversions ----------------
__global__ void conv_q(const float* __restrict__ q) {
    int i = blockIdx.x * 256 + threadIdx.x;
    float x = q[i];
    __nv_bfloat16 h = __float2bfloat16(x);
    g_qhi[i] = h;
    g_qlo[i] = __float2bfloat16(x - __bfloat162float(h));
}

__global__ void conv_w() {
    int i = blockIdx.x * 256 + threadIdx.x;
    int k = i / LDQ, n = i % LDQ;
    float x = g_Wbig[i];
    __nv_bfloat16 h = __float2bfloat16(x);
    g_wbhi[n * C_ + k] = h;
    g_wblo[n * C_ + k] = __float2bfloat16(x - __bfloat162float(h));
}

// ---------------- small fp32 SGEMM (W_A = Wv @ W1_top) ----------------
__global__ __launch_bounds__(256) void sgemm128(
    const float* __restrict__ Aex, const float* __restrict__ Bex,
    int flags, int M, int N, int K, int ldA, int ldB, int ldC)
{
    const float* A  = Aex;
    const float* Bm = Bex;
    float* Cm       = (flags & F_DST_WBIG) ? g_Wbig : g_Q;

    __shared__ float As[2][8][132];
    __shared__ float Bs[2][8][128];

    const int tid = threadIdx.x;
    const int tx = tid & 15;
    const int ty = tid >> 4;
    const int rowBase = blockIdx.y * 128;
    const int colBase = blockIdx.x * 128;

    const int arow = tid >> 1, acol = (tid & 1) * 4;
    const int brow = tid >> 5, bcol = (tid & 31) * 4;

    const float* Aptr = A + (size_t)(rowBase + arow) * ldA + acol;
    const float* Bptr = Bm + (size_t)brow * ldB + colBase + bcol;

    float4 aReg = *(const float4*)Aptr;
    float4 bReg = *(const float4*)Bptr;

    float acc[8][8];
#pragma unroll
    for (int i = 0; i < 8; i++)
#pragma unroll
        for (int j = 0; j < 8; j++) acc[i][j] = 0.f;

    As[0][acol + 0][arow] = aReg.x; As[0][acol + 1][arow] = aReg.y;
    As[0][acol + 2][arow] = aReg.z; As[0][acol + 3][arow] = aReg.w;
    *(float4*)&Bs[0][brow][bcol] = bReg;
    __syncthreads();

    const int nIter = K >> 3;
    int buf = 0;
    for (int it = 0; it < nIter; it++) {
        if (it + 1 < nIter) {
            aReg = *(const float4*)(Aptr + (it + 1) * 8);
            bReg = *(const float4*)(Bptr + (size_t)(it + 1) * 8 * ldB);
        }
#pragma unroll
        for (int kk = 0; kk < 8; kk++) {
            float4 a0 = *(const float4*)&As[buf][kk][ty * 4];
            float4 a1 = *(const float4*)&As[buf][kk][64 + ty * 4];
            float4 b0 = *(const float4*)&Bs[buf][kk][tx * 4];
            float4 b1 = *(const float4*)&Bs[buf][kk][64 + tx * 4];
            float am[8] = {a0.x, a0.y, a0.z, a0.w, a1.x, a1.y, a1.z, a1.w};
            float bn[8] = {b0.x, b0.y, b0.z, b0.w, b1.x, b1.y, b1.z, b1.w};
#pragma unroll
            for (int i = 0; i < 8; i++)
#pragma unroll
                for (int j = 0; j < 8; j++)
                    acc[i][j] = fmaf(am[i], bn[j], acc[i][j]);
        }
        if (it + 1 < nIter) {
            int nb = buf ^ 1;
            As[nb][acol + 0][arow] = aReg.x; As[nb][acol + 1][arow] = aReg.y;
            As[nb][acol + 2][arow] = aReg.z; As[nb][acol + 3][arow] = aReg.w;
            *(float4*)&Bs[nb][brow][bcol] = bReg;
            __syncthreads();
            buf = nb;
        }
    }
#pragma unroll
    for (int i = 0; i < 8; i++) {
        int r = rowBase + ((i < 4) ? (ty * 4 + i) : (64 + ty * 4 + i - 4));
        float* crow = Cm + (size_t)r * ldC + colBase;
        *(float4*)(crow + tx * 4) =
            make_float4(acc[i][0], acc[i][1], acc[i][2], acc[i][3]);
        *(float4*)(crow + 64 + tx * 4) =
            make_float4(acc[i][4], acc[i][5], acc[i][6], acc[i][7]);
    }
}

// ================= mma.sync split-bf16 GEMM: g_Q = q @ Wbig + bcat =================
// CTA 128x64, 8 warps (4x2), warp 32x32. K in 6 chunks of 64.
// Smem rows padded to 72 bf16 (144B): conflict-free ldmatrix.
#define GS_AHI 0
#define GS_ALO 18432
#define GS_BHI 36864
#define GS_BLO 46080
#define GS_TOT 55296

__device__ __forceinline__ unsigned smem_u32(const void* p) {
    unsigned a;
    asm("{ .reg .u64 t; cvta.to.shared.u64 t, %1; cvt.u32.u64 %0, t; }" : "=r"(a) : "l"(p));
    return a;
}
#define LDSM4(rg, addr) \
    asm volatile("ldmatrix.sync.aligned.m8n8.x4.shared.b16 {%0,%1,%2,%3}, [%4];" \
        : "=r"((rg)[0]), "=r"((rg)[1]), "=r"((rg)[2]), "=r"((rg)[3]) : "r"(addr))
#define MMA16816(d, a, b0, b1) \
    asm volatile("mma.sync.aligned.m16n8k16.row.col.f32.bf16.bf16.f32 " \
        "{%0,%1,%2,%3}, {%4,%5,%6,%7}, {%8,%9}, {%0,%1,%2,%3};" \
        : "+f"((d)[0]), "+f"((d)[1]), "+f"((d)[2]), "+f"((d)[3]) \
        : "r"((a)[0]), "r"((a)[1]), "r"((a)[2]), "r"((a)[3]), "r"(b0), "r"(b1))

__global__ __launch_bounds__(256) void gemm_mma() {
    extern __shared__ char sm[];
    const unsigned sb = smem_u32(sm);
    const int tid = threadIdx.x;
    const int w = tid >> 5, lane = tid & 31;
    const int rowBase = blockIdx.y * 128;
    const int colBase = blockIdx.x * 64;
    const int wm = (w & 3) * 32;     // warp M offset
    const int wn = (w >> 2) * 32;    // warp N offset

    float acc[2][4][4];
#pragma unroll
    for (int mt = 0; mt < 2; mt++)
#pragma unroll
        for (int nt = 0; nt < 4; nt++)
#pragma unroll
            for (int j = 0; j < 4; j++) acc[mt][nt][j] = 0.f;

    // precomputed ldmatrix lane addresses (chunk-invariant part)
    const unsigned aRow = (lane & 15);
    const unsigned aKb  = (lane >> 4) << 4;
    const unsigned bRow = (lane & 7) + ((lane >> 4) << 3);
    const unsigned bKb  = ((lane >> 3) & 1) << 4;

    for (int kc = 0; kc < 6; kc++) {
        for (int i = tid; i < 1024; i += 256) {        // A: 128x64 bf16, 8 uint4/row
            int r = i >> 3, c = i & 7;
            size_t g = (size_t)(rowBase + r) * C_ + kc * 64 + c * 8;
            *(uint4*)(sm + GS_AHI + r * 144 + c * 16) = *(const uint4*)(g_qhi + g);
            *(uint4*)(sm + GS_ALO + r * 144 + c * 16) = *(const uint4*)(g_qlo + g);
        }
        for (int i = tid; i < 512; i += 256) {         // B: 64x64 bf16
            int r = i >> 3, c = i & 7;
            size_t g = (size_t)(colBase + r) * C_ + kc * 64 + c * 8;
            *(uint4*)(sm + GS_BHI + r * 144 + c * 16) = *(const uint4*)(g_wbhi + g);
            *(uint4*)(sm + GS_BLO + r * 144 + c * 16) = *(const uint4*)(g_wblo + g);
        }
        __syncthreads();

#pragma unroll
        for (int ks = 0; ks < 4; ks++) {
            unsigned ahi[2][4], alo[2][4], bhi[2][4], blo[2][4];
#pragma unroll
            for (int mt = 0; mt < 2; mt++) {
                unsigned addr = sb + GS_AHI + (wm + mt * 16 + aRow) * 144 + ks * 32 + aKb;
                LDSM4(ahi[mt], addr);
                LDSM4(alo[mt], addr + (GS_ALO - GS_AHI));
            }
#pragma unroll
            for (int ng = 0; ng < 2; ng++) {           // two n16 groups
                unsigned addr = sb + GS_BHI + (wn + ng * 16 + bRow) * 144 + ks * 32 + bKb;
                LDSM4(bhi[ng], addr);
                LDSM4(blo[ng], addr + (GS_BLO - GS_BHI));
            }
#pragma unroll
            for (int mt = 0; mt < 2; mt++)
#pragma unroll
                for (int nt = 0; nt < 4; nt++) {
                    unsigned bh0 = bhi[nt >> 1][(nt & 1) * 2];
                    unsigned bh1 = bhi[nt >> 1][(nt & 1) * 2 + 1];
                    unsigned bl0 = blo[nt >> 1][(nt & 1) * 2];
                    unsigned bl1 = blo[nt >> 1][(nt & 1) * 2 + 1];
                    MMA16816(acc[mt][nt], ahi[mt], bh0, bh1);   // hi*hi
                    MMA16816(acc[mt][nt], ahi[mt], bl0, bl1);   // hi*lo
                    MMA16816(acc[mt][nt], alo[mt], bh0, bh1);   // lo*hi
                }
        }
        __syncthreads();
    }

    // epilogue: direct stores + bias
#pragma unroll
    for (int mt = 0; mt < 2; mt++) {
        int m0 = rowBase + wm + mt * 16 + (lane >> 2);
#pragma unroll
        for (int nt = 0; nt < 4; nt++) {
            int c = colBase + wn + nt * 8 + 2 * (lane & 3);
            float bb0 = g_bcat[c], bb1 = g_bcat[c + 1];
            float* p0 = g_Q + (size_t)m0 * LDQ + c;
            float* p1 = g_Q + (size_t)(m0 + 8) * LDQ + c;
            p0[0] = acc[mt][nt][0] + bb0; p0[1] = acc[mt][nt][1] + bb1;
            p1[0] = acc[mt][nt][2] + bb0; p1[1] = acc[mt][nt][3] + bb1;
        }
    }
}

// ---------------- comparator ----------------
__device__ __forceinline__ bool dless(float d1, int i1, float d2, int i2) {
    return (d1 < d2) || (d1 == d2 && i1 < i2);
}
__device__ __forceinline__ float warp_sort32(float m, int lane) {
#pragma unroll
    for (int k = 2; k <= 32; k <<= 1) {
#pragma unroll
        for (int j = k >> 1; j > 0; j >>= 1) {
            float other = __shfl_xor_sync(0xffffffffu, m, j);
            bool up = ((lane & k) == 0);
            bool lower = ((lane & j) == 0);
            float mn = fminf(m, other), mx = fmaxf(m, other);
            m = (lower == up) ? mn : mx;
        }
    }
    return m;
}

// ---------------- kNN ----------------
__global__ __launch_bounds__(256) void knn_kernel(const float* __restrict__ q_pos) {
    __shared__ float4 sP[N_];
    __shared__ float  sBd[8][CAP_];
    __shared__ int    sBi[8][CAP_];
    const int qbase = blockIdx.x * 8;
    const int b = qbase >> 11;
    const float* P = q_pos + (size_t)b * N_ * 3;
    for (int i = threadIdx.x; i < N_; i += 256) {
        float x = P[i * 3 + 0], y = P[i * 3 + 1], z = P[i * 3 + 2];
        sP[i] = make_float4(x, y, z, x * x + y * y + z * z);
    }
    __syncthreads();
    const int w = threadIdx.x >> 5, lane = threadIdx.x & 31;
    const float FINF = __int_as_float(0x7f800000);

    const int qi = qbase + w;
    const float4 Q = sP[qi & (N_ - 1)];

    float m = FINF;
    for (int t = 0; t < N_ / 32; t++) {
        float4 c = sP[t * 32 + lane];
        float dot = Q.x * c.x + Q.y * c.y + Q.z * c.z;
        float dd = fmaf(dot, -2.f, c.w + Q.w);
        m = fminf(m, dd);
    }
    float s = warp_sort32(m, lane);
    float T    = __shfl_sync(0xffffffffu, s, K_ - 1);
    float Tmax = __shfl_sync(0xffffffffu, s, 31);

    int cnt = 0;
    float Tuse = T;
    for (int attempt = 0; attempt < 2; attempt++) {
        cnt = 0;
        for (int t = 0; t < N_ / 32; t++) {
            int cand = t * 32 + lane;
            float4 c = sP[cand];
            float dot = Q.x * c.x + Q.y * c.y + Q.z * c.z;
            float dd = fmaf(dot, -2.f, c.w + Q.w);
            bool p = (dd <= Tuse);
            unsigned mask = __ballot_sync(0xffffffffu, p);
            if (p) {
                int pos = cnt + __popc(mask & ((1u << lane) - 1u));
                if (pos < CAP_) { sBd[w][pos] = dd; sBi[w][pos] = cand; }
            }
            cnt += __popc(mask);
        }
        if (cnt >= K_) break;
        Tuse = Tmax;
    }
    int n = cnt < CAP_ ? cnt : CAP_;
    __syncwarp();

    float mnx = FINF, mny = FINF, mnz = FINF;
    float mxx = -FINF, mxy = -FINF, mxz = -FINF;
    for (int r = 0; r < K_; r++) {
        float bd = FINF; int bi = 0x7fffffff;
        for (int i = lane; i < n; i += 32) {
            float dd = sBd[w][i]; int ii = sBi[w][i];
            if (dless(dd, ii, bd, bi)) { bd = dd; bi = ii; }
        }
#pragma unroll
        for (int off = 16; off; off >>= 1) {
            float od = __shfl_xor_sync(0xffffffffu, bd, off);
            int   oi = __shfl_xor_sync(0xffffffffu, bi, off);
            if (dless(od, oi, bd, bi)) { bd = od; bi = oi; }
        }
        if (lane == 0) g_knn[qi * K_ + r] = bi;
        float4 wp = sP[bi];
        mnx = fminf(mnx, wp.x); mxx = fmaxf(mxx, wp.x);
        mny = fminf(mny, wp.y); mxy = fmaxf(mxy, wp.y);
        mnz = fminf(mnz, wp.z); mxz = fmaxf(mxz, wp.z);
        for (int i = lane; i < n; i += 32)
            if (sBi[w][i] == bi) sBd[w][i] = FINF;
        __syncwarp();
    }
    if (lane == 0) {
        g_scale[qi * 3 + 0] = (mxx - mnx) * 0.5f;
        g_scale[qi * 3 + 1] = (mxy - mny) * 0.5f;
        g_scale[qi * 3 + 2] = (mxz - mnz) * 0.5f;
    }
}

// ---------------- per-point MLP ----------------
__global__ __launch_bounds__(256) void offset_kernel(
    const float* __restrict__ q_pos, const float* __restrict__ ln_g,
    const float* __restrict__ ln_b, const float* __restrict__ W2)
{
    const int w = threadIdx.x >> 5, lane = threadIdx.x & 31;
    const int p = blockIdx.x * 8 + w;
    const int b = p >> 11;
    const int c0 = lane * 12;

    float4 bq[3], lg[3], lb[3], w2f[9];
    const float* Bq = g_Q + (size_t)p * LDQ + C_ + c0;
#pragma unroll
    for (int t = 0; t < 3; t++) {
        bq[t] = *(const float4*)(Bq + t * 4);
        lg[t] = *(const float4*)(ln_g + c0 + t * 4);
        lb[t] = *(const float4*)(ln_b + c0 + t * 4);
    }
#pragma unroll
    for (int t = 0; t < 9; t++) w2f[t] = *(const float4*)(W2 + c0 * 3 + t * 4);
    const float* w2s = (const float*)w2f;
    const float* bqs = (const float*)bq;
    const float* lgs = (const float*)lg;
    const float* lbs = (const float*)lb;

    const float sx = g_scale[p * 3 + 0];
    const float sy = g_scale[p * 3 + 1];
    const float sz = g_scale[p * 3 + 2];

    for (int k = 0; k < K_; k++) {
        const int nb = g_knn[p * K_ + k];
        const int rownb = b * N_ + nb;
        const float* Arow = g_Q + (size_t)rownb * LDQ + c0;

        float h[12];
        float4 a0 = *(const float4*)(Arow);
        float4 a1 = *(const float4*)(Arow + 4);
        float4 a2 = *(const float4*)(Arow + 8);
        h[0] = a0.x + bqs[0]; h[1] = a0.y + bqs[1]; h[2] = a0.z + bqs[2]; h[3] = a0.w + bqs[3];
        h[4] = a1.x + bqs[4]; h[5] = a1.y + bqs[5]; h[6] = a1.z + bqs[6]; h[7] = a1.w + bqs[7];
        h[8] = a2.x + bqs[8]; h[9] = a2.y + bqs[9]; h[10]= a2.z + bqs[10];h[11]= a2.w + bqs[11];

        float s = 0.f;
#pragma unroll
        for (int j = 0; j < 12; j++) s += h[j];
#pragma unroll
        for (int off = 16; off; off >>= 1) s += __shfl_xor_sync(0xffffffffu, s, off);
        float mu = s * (1.f / C_);
        float v = 0.f;
#pragma unroll
        for (int j = 0; j < 12; j++) { float t = h[j] - mu; v += t * t; }
#pragma unroll
        for (int off = 16; off; off >>= 1) v += __shfl_xor_sync(0xffffffffu, v, off);
        float rstd = rsqrtf(v * (1.f / C_) + 1e-5f);

        float s0 = 0.f, s1 = 0.f, s2 = 0.f;
#pragma unroll
        for (int j = 0; j < 12; j++) {
            float g = (h[j] - mu) * rstd * lgs[j] + lbs[j];
            float y = 0.5f * g * (1.f + erff(g * 0.70710678118654752f));
            s0 = fmaf(y, w2s[j * 3 + 0], s0);
            s1 = fmaf(y, w2s[j * 3 + 1], s1);
            s2 = fmaf(y, w2s[j * 3 + 2], s2);
        }
#pragma unroll
        for (int off = 16; off; off >>= 1) {
            s0 += __shfl_xor_sync(0xffffffffu, s0, off);
            s1 += __shfl_xor_sync(0xffffffffu, s1, off);
            s2 += __shfl_xor_sync(0xffffffffu, s2, off);
        }
        if (lane == 0) {
            const int e = p * K_ + k;
            const float* pp = q_pos + (size_t)rownb * 3;
            g_shift[e * 3 + 0] = fmaf(tanhf(s0), sx, pp[0]);
            g_shift[e * 3 + 1] = fmaf(tanhf(s1), sy, pp[1]);
            g_shift[e * 3 + 2] = fmaf(tanhf(s2), sz, pp[2]);
        }
    }
}

// ---------------- three_nn ----------------
__global__ __launch_bounds__(256) void three_nn_kernel(const float* __restrict__ q_pos) {
    __shared__ float4 sP[N_];
    const int ebase = blockIdx.x * 64;
    const int b = ebase / (N_ * K_);
    const float* P = q_pos + (size_t)b * N_ * 3;
    for (int i = threadIdx.x; i < N_; i += 256) {
        float x = P[i * 3 + 0], y = P[i * 3 + 1], z = P[i * 3 + 2];
        sP[i] = make_float4(x, y, z, x * x + y * y + z * z);
    }
    __syncthreads();
    const int w = threadIdx.x >> 5, lane = threadIdx.x & 31;
    const float FINF = __int_as_float(0x7f800000);

    for (int sub = 0; sub < 8; sub++) {
        const int e = ebase + w * 8 + sub;
        const float px = g_shift[e * 3 + 0];
        const float py = g_shift[e * 3 + 1];
        const float pz = g_shift[e * 3 + 2];
        const float qw = px * px + py * py + pz * pz;

        float d0 = FINF, d1 = FINF, d2 = FINF;
        int   i0 = 0x7fffffff, i1 = 0x7fffffff, i2 = 0x7fffffff;
        for (int t = 0; t < N_ / 32; t++) {
            int cand = t * 32 + lane;
            float4 c = sP[cand];
            float dot = px * c.x + py * c.y + pz * c.z;
            float dd = fmaf(dot, -2.f, c.w + qw);
            if (dless(dd, cand, d2, i2)) {
                d2 = dd; i2 = cand;
                if (dless(d2, i2, d1, i1)) {
                    float td = d1; d1 = d2; d2 = td;
                    int ti = i1; i1 = i2; i2 = ti;
                    if (dless(d1, i1, d0, i0)) {
                        td = d0; d0 = d1; d1 = td;
                        ti = i0; i0 = i1; i1 = ti;
                    }
                }
            }
        }
        float rd[3]; int ri[3];
#pragma unroll
        for (int r = 0; r < 3; r++) {
            float bd = d0; int bi = i0;
#pragma unroll
            for (int off = 16; off; off >>= 1) {
                float od = __shfl_xor_sync(0xffffffffu, bd, off);
                int   oi = __shfl_xor_sync(0xffffffffu, bi, off);
                if (dless(od, oi, bd, bi)) { bd = od; bi = oi; }
            }
            rd[r] = bd; ri[r] = bi;
            if (i0 == bi) { d0 = d1; i0 = i1; d1 = d2; i1 = i2; d2 = FINF; i2 = 0x7fffffff; }
        }
        if (lane == 0) {
            float r0 = 1.f / (rd[0] + 1e-8f);
            float r1 = 1.f / (rd[1] + 1e-8f);
            float r2 = 1.f / (rd[2] + 1e-8f);
            float sm = r0 + r1 + r2;
            g_i3[e * 3 + 0] = ri[0]; g_w3[e * 3 + 0] = r0 / sm;
            g_i3[e * 3 + 1] = ri[1]; g_w3[e * 3 + 1] = r1 / sm;
            g_i3[e * 3 + 2] = ri[2]; g_w3[e * 3 + 2] = r2 / sm;
        }
    }
}

// ---------------- final ----------------
__global__ __launch_bounds__(96) void final_kernel(float* __restrict__ out) {
    const int row = blockIdx.x;
    const int b = row >> 11;
    const int tid = threadIdx.x;
    __shared__ int   sI[K_ * 3];
    __shared__ float sW[K_ * 3];
    const int e0 = row * K_;
    if (tid < K_ * 3) { sI[tid] = g_i3[e0 * 3 + tid]; sW[tid] = g_w3[e0 * 3 + tid]; }
    __syncthreads();

    const size_t baseB = (size_t)b * N_ * LDQ;
    float4 qp = *(const float4*)(g_Q + (size_t)row * LDQ + 3 * C_ + tid * 4);
    const float NINF = __int_as_float(0xff800000);
    float4 mx = make_float4(NINF, NINF, NINF, NINF);

    for (int k = 0; k < K_; k++) {
        int   a0 = sI[3 * k + 0], a1 = sI[3 * k + 1], a2 = sI[3 * k + 2];
        float w0 = sW[3 * k + 0], w1 = sW[3 * k + 1], w2 = sW[3 * k + 2];
        float4 r0 = *(const float4*)(g_Q + baseB + (size_t)a0 * LDQ + 2 * C_ + tid * 4);
        float4 r1 = *(const float4*)(g_Q + baseB + (size_t)a1 * LDQ + 2 * C_ + tid * 4);
        float4 r2 = *(const float4*)(g_Q + baseB + (size_t)a2 * LDQ + 2 * C_ + tid * 4);
        float v0 = qp.x + w0 * r0.x + w1 * r1.x + w2 * r2.x;
        float v1 = qp.y + w0 * r0.y + w1 * r1.y + w2 * r2.y;
        float v2 = qp.z + w0 * r0.z + w1 * r1.z + w2 * r2.z;
        float v3 = qp.w + w0 * r0.w + w1 * r1.w + w2 * r2.w;
        v0 = v0 > 0.f ? v0 : 0.2f * v0;
        v1 = v1 > 0.f ? v1 : 0.2f * v1;
        v2 = v2 > 0.f ? v2 : 0.2f * v2;
        v3 = v3 > 0.f ? v3 : 0.2f * v3;
        mx.x = fmaxf(mx.x, v0); mx.y = fmaxf(mx.y, v1);
        mx.z = fmaxf(mx.z, v2); mx.w = fmaxf(mx.w, v3);
    }
    *(float4*)(out + (size_t)row * C_ + tid * 4) = mx;
}

// ---------------- launch ----------------
extern "C" void kernel_launch(void* const* d_in, const int* in_sizes, int n_in,
                              void* d_out, int out_size) {
    const float* q     = (const float*)d_in[0];
    const float* q_pos = (const float*)d_in[1];
    const float* Wv    = (const float*)d_in[2];
    const float* bv    = (const float*)d_in[3];
    const float* W1    = (const float*)d_in[4];
    const float* b1    = (const float*)d_in[5];
    const float* ln_g  = (const float*)d_in[6];
    const float* ln_b  = (const float*)d_in[7];
    const float* W2    = (const float*)d_in[8];
    const float* Wk    = (const float*)d_in[9];
    const float* bk    = (const float*)d_in[10];

    cudaFuncSetAttribute(gemm_mma, cudaFuncAttributeMaxDynamicSharedMemorySize, GS_TOT);

    prep_wbig<<<(C_ * (LDQ - C_) + 255) / 256, 256>>>(W1, Wk);
    prep_bias<<<48 + (LDQ - C_ + 255) / 256, 256>>>(bv, W1, b1, bk);
    // W_A = Wv @ W1_top -> g_Wbig cols [0,384)
    sgemm128<<<dim3(C_ / 128, C_ / 128), 256>>>(Wv, W1, F_DST_WBIG,
                                                C_, C_, C_, C_, C_, LDQ);
    conv_w<<<(C_ * LDQ) / 256, 256>>>();
    conv_q<<<(ROWS_ * C_) / 256, 256>>>(q);
    knn_kernel<<<ROWS_ / 8, 256>>>(q_pos);
    // g_Q = q @ Wbig + bcat  (split-bf16 mma.sync)
    gemm_mma<<<dim3(LDQ / 64, ROWS_ / 128), 256, GS_TOT>>>();
    offset_kernel<<<ROWS_ / 8, 256>>>(q_pos, ln_g, ln_b, W2);
    three_nn_kernel<<<EDGES_ / 64, 256>>>(q_pos);
    final_kernel<<<ROWS_, 96>>>((float*)d_out);
}

// round 11
// speedup vs baseline: 1.4470x; 1.0148x over previous
#include <cuda_runtime.h>
#include <cuda_bf16.h>
#include <math.h>

#define B_ 4
#define N_ 2048
#define C_ 384
#define K_ 10
#define ROWS_ (B_*N_)      // 8192
#define EDGES_ (ROWS_*K_)  // 81920
#define LDQ 1536
#define CAP_ 224

// ---------------- scratch ----------------
__device__ float g_Q[ROWS_*LDQ];
__device__ float g_Wbig[C_*LDQ];            // fp32 [k][n]
__device__ float g_bcat[LDQ];
__device__ __nv_bfloat16 g_qhi[ROWS_*C_];   // q split, [M,K]
__device__ __nv_bfloat16 g_qlo[ROWS_*C_];
__device__ __nv_bfloat16 g_wbhi[C_*LDQ];    // Wbig split, [K,N] (same layout as g_Wbig)
__device__ __nv_bfloat16 g_wblo[C_*LDQ];
__device__ int   g_knn[ROWS_*K_];
__device__ float g_scale[ROWS_*3];
__device__ float g_shift[EDGES_*3];
__device__ int   g_i3[EDGES_*3];
__device__ float g_w3[EDGES_*3];

#define F_DST_WBIG 2

// ---------------- weight prep: cols 384..1536 of Wbig ----------------
__global__ void prep_wbig(const float* __restrict__ W1, const float* __restrict__ Wk) {
    int i = blockIdx.x * 256 + threadIdx.x;
    if (i >= C_ * (LDQ - C_)) return;
    int r = i / (LDQ - C_), c = i % (LDQ - C_);
    float v;
    if (c < C_)            v = W1[(C_ + r) * C_ + c];
    else if (c < 2 * C_)   v = Wk[r * C_ + (c - C_)];
    else                   v = Wk[(C_ + r) * C_ + (c - 2*C_)] - Wk[r * C_ + (c - 2*C_)];
    g_Wbig[r * LDQ + C_ + c] = v;
}

__global__ __launch_bounds__(256) void prep_bias(
    const float* __restrict__ bv, const float* __restrict__ W1,
    const float* __restrict__ b1, const float* __restrict__ bk)
{
    if (blockIdx.x < 48) {
        int w = threadIdx.x >> 5, lane = threadIdx.x & 31;
        int o = blockIdx.x * 8 + w;
        float s = 0.f;
        for (int t = 0; t < 12; t++) {
            int j = t * 32 + lane;
            s = fmaf(bv[j], W1[j * C_ + o], s);
        }
#pragma unroll
        for (int off = 16; off; off >>= 1) s += __shfl_xor_sync(0xffffffffu, s, off);
        if (lane == 0) g_bcat[o] = s;
    } else {
        int i = (blockIdx.x - 48) * 256 + threadIdx.x;
        if (i >= LDQ - C_) return;
        float v;
        if (i < C_)            v = b1[i];
        else if (i < 2 * C_)   v = 0.f;
        else                   v = bk[i - 2 * C_];
        g_bcat[C_ + i] = v;
    }
}

// ---------------- split conversions (both fully coalesced) ----------------
__global__ void conv_q(const float* __restrict__ q) {
    int i = blockIdx.x * 256 + threadIdx.x;
    float x = q[i];
    __nv_bfloat16 h = __float2bfloat16(x);
    g_qhi[i] = h;
    g_qlo[i] = __float2bfloat16(x - __bfloat162float(h));
}

__global__ void conv_w() {
    int i = blockIdx.x * 256 + threadIdx.x;   // [k][n], same layout both sides
    float x = g_Wbig[i];
    __nv_bfloat16 h = __float2bfloat16(x);
    g_wbhi[i] = h;
    g_wblo[i] = __float2bfloat16(x - __bfloat162float(h));
}

// ---------------- small fp32 SGEMM (W_A = Wv @ W1_top) ----------------
__global__ __launch_bounds__(256) void sgemm128(
    const float* __restrict__ Aex, const float* __restrict__ Bex,
    int flags, int M, int N, int K, int ldA, int ldB, int ldC)
{
    const float* A  = Aex;
    const float* Bm = Bex;
    float* Cm       = (flags & F_DST_WBIG) ? g_Wbig : g_Q;

    __shared__ float As[2][8][132];
    __shared__ float Bs[2][8][128];

    const int tid = threadIdx.x;
    const int tx = tid & 15;
    const int ty = tid >> 4;
    const int rowBase = blockIdx.y * 128;
    const int colBase = blockIdx.x * 128;

    const int arow = tid >> 1, acol = (tid & 1) * 4;
    const int brow = tid >> 5, bcol = (tid & 31) * 4;

    const float* Aptr = A + (size_t)(rowBase + arow) * ldA + acol;
    const float* Bptr = Bm + (size_t)brow * ldB + colBase + bcol;

    float4 aReg = *(const float4*)Aptr;
    float4 bReg = *(const float4*)Bptr;

    float acc[8][8];
#pragma unroll
    for (int i = 0; i < 8; i++)
#pragma unroll
        for (int j = 0; j < 8; j++) acc[i][j] = 0.f;

    As[0][acol + 0][arow] = aReg.x; As[0][acol + 1][arow] = aReg.y;
    As[0][acol + 2][arow] = aReg.z; As[0][acol + 3][arow] = aReg.w;
    *(float4*)&Bs[0][brow][bcol] = bReg;
    __syncthreads();

    const int nIter = K >> 3;
    int buf = 0;
    for (int it = 0; it < nIter; it++) {
        if (it + 1 < nIter) {
            aReg = *(const float4*)(Aptr + (it + 1) * 8);
            bReg = *(const float4*)(Bptr + (size_t)(it + 1) * 8 * ldB);
        }
#pragma unroll
        for (int kk = 0; kk < 8; kk++) {
            float4 a0 = *(const float4*)&As[buf][kk][ty * 4];
            float4 a1 = *(const float4*)&As[buf][kk][64 + ty * 4];
            float4 b0 = *(const float4*)&Bs[buf][kk][tx * 4];
            float4 b1 = *(const float4*)&Bs[buf][kk][64 + tx * 4];
            float am[8] = {a0.x, a0.y, a0.z, a0.w, a1.x, a1.y, a1.z, a1.w};
            float bn[8] = {b0.x, b0.y, b0.z, b0.w, b1.x, b1.y, b1.z, b1.w};
#pragma unroll
            for (int i = 0; i < 8; i++)
#pragma unroll
                for (int j = 0; j < 8; j++)
                    acc[i][j] = fmaf(am[i], bn[j], acc[i][j]);
        }
        if (it + 1 < nIter) {
            int nb = buf ^ 1;
            As[nb][acol + 0][arow] = aReg.x; As[nb][acol + 1][arow] = aReg.y;
            As[nb][acol + 2][arow] = aReg.z; As[nb][acol + 3][arow] = aReg.w;
            *(float4*)&Bs[nb][brow][bcol] = bReg;
            __syncthreads();
            buf = nb;
        }
    }
#pragma unroll
    for (int i = 0; i < 8; i++) {
        int r = rowBase + ((i < 4) ? (ty * 4 + i) : (64 + ty * 4 + i - 4));
        float* crow = Cm + (size_t)r * ldC + colBase;
        *(float4*)(crow + tx * 4) =
            make_float4(acc[i][0], acc[i][1], acc[i][2], acc[i][3]);
        *(float4*)(crow + 64 + tx * 4) =
            make_float4(acc[i][4], acc[i][5], acc[i][6], acc[i][7]);
    }
}

// ================= mma.sync split-bf16 GEMM, cp.async double-buffered =============
#define GA_HI 0
#define GA_LO 18432
#define GB_HI 36864
#define GB_LO 46080
#define G_STG 55296
#define G_TOT (2*G_STG)     // 110592

__device__ __forceinline__ unsigned smem_u32(const void* p) {
    unsigned a;
    asm("{ .reg .u64 t; cvta.to.shared.u64 t, %1; cvt.u32.u64 %0, t; }" : "=r"(a) : "l"(p));
    return a;
}
#define CP16(dst, src) \
    asm volatile("cp.async.cg.shared.global [%0], [%1], 16;" :: "r"(dst), "l"(src))
#define CP_COMMIT() asm volatile("cp.async.commit_group;" ::: "memory")
#define CP_WAIT0()  asm volatile("cp.async.wait_group 0;" ::: "memory")
#define CP_WAIT1()  asm volatile("cp.async.wait_group 1;" ::: "memory")
#define LDSM4(rg, addr) \
    asm volatile("ldmatrix.sync.aligned.m8n8.x4.shared.b16 {%0,%1,%2,%3}, [%4];" \
        : "=r"((rg)[0]), "=r"((rg)[1]), "=r"((rg)[2]), "=r"((rg)[3]) : "r"(addr))
#define LDSM4T(rg, addr) \
    asm volatile("ldmatrix.sync.aligned.m8n8.x4.trans.shared.b16 {%0,%1,%2,%3}, [%4];" \
        : "=r"((rg)[0]), "=r"((rg)[1]), "=r"((rg)[2]), "=r"((rg)[3]) : "r"(addr))
#define MMA16816(d, a, b0, b1) \
    asm volatile("mma.sync.aligned.m16n8k16.row.col.f32.bf16.bf16.f32 " \
        "{%0,%1,%2,%3}, {%4,%5,%6,%7}, {%8,%9}, {%0,%1,%2,%3};" \
        : "+f"((d)[0]), "+f"((d)[1]), "+f"((d)[2]), "+f"((d)[3]) \
        : "r"((a)[0]), "r"((a)[1]), "r"((a)[2]), "r"((a)[3]), "r"(b0), "r"(b1))

__device__ __forceinline__ void gemm_load_stage(
    unsigned base, int kc, int rowBase, int colBase, int tid)
{
#pragma unroll
    for (int t = 0; t < 4; t++) {              // A: 1024 x 16B per half
        int i = tid + t * 256;
        int r = i >> 3, c = i & 7;
        unsigned off = r * 144 + c * 16;
        size_t g = (size_t)(rowBase + r) * C_ + kc * 64 + c * 8;
        CP16(base + GA_HI + off, (const void*)(g_qhi + g));
        CP16(base + GA_LO + off, (const void*)(g_qlo + g));
    }
#pragma unroll
    for (int t = 0; t < 2; t++) {              // B: 512 x 16B per half, [k][n]
        int i = tid + t * 256;
        int r = i >> 3, c = i & 7;
        unsigned off = r * 144 + c * 16;
        size_t g = (size_t)(kc * 64 + r) * LDQ + colBase + c * 8;
        CP16(base + GB_HI + off, (const void*)(g_wbhi + g));
        CP16(base + GB_LO + off, (const void*)(g_wblo + g));
    }
}

__global__ __launch_bounds__(256) void gemm_mma() {
    extern __shared__ char sm[];
    const unsigned sb = smem_u32(sm);
    const int tid = threadIdx.x;
    const int w = tid >> 5, lane = tid & 31;
    const int rowBase = blockIdx.y * 128;
    const int colBase = blockIdx.x * 64;
    const int wm = (w & 3) * 32;
    const int wn = (w >> 2) * 32;

    float acc[2][4][4];
#pragma unroll
    for (int mt = 0; mt < 2; mt++)
#pragma unroll
        for (int nt = 0; nt < 4; nt++)
#pragma unroll
            for (int j = 0; j < 4; j++) acc[mt][nt][j] = 0.f;

    const unsigned aRow = (lane & 15);
    const unsigned aKb  = (lane >> 4) << 4;
    const unsigned bK   = (lane & 7) + ((lane >> 3) & 1) * 8;
    const unsigned bN   = ((lane >> 4) & 1) * 8;

    gemm_load_stage(sb, 0, rowBase, colBase, tid);
    CP_COMMIT();

    for (int kc = 0; kc < 6; kc++) {
        const unsigned buf = sb + (kc & 1) * G_STG;
        if (kc + 1 < 6) {
            gemm_load_stage(sb + ((kc + 1) & 1) * G_STG, kc + 1, rowBase, colBase, tid);
            CP_COMMIT();
            CP_WAIT1();
        } else {
            CP_WAIT0();
        }
        __syncthreads();

#pragma unroll
        for (int ks = 0; ks < 4; ks++) {
            unsigned ahi[2][4], alo[2][4], bhi[2][4], blo[2][4];
#pragma unroll
            for (int mt = 0; mt < 2; mt++) {
                unsigned addr = buf + GA_HI + (wm + mt * 16 + aRow) * 144 + ks * 32 + aKb;
                LDSM4(ahi[mt], addr);
                LDSM4(alo[mt], addr + (GA_LO - GA_HI));
            }
#pragma unroll
            for (int ng = 0; ng < 2; ng++) {
                unsigned addr = buf + GB_HI + (ks * 16 + bK) * 144 + (wn + ng * 16 + bN) * 2;
                LDSM4T(bhi[ng], addr);
                LDSM4T(blo[ng], addr + (GB_LO - GB_HI));
            }
#pragma unroll
            for (int mt = 0; mt < 2; mt++)
#pragma unroll
                for (int nt = 0; nt < 4; nt++) {
                    unsigned bh0 = bhi[nt >> 1][(nt & 1) * 2];
                    unsigned bh1 = bhi[nt >> 1][(nt & 1) * 2 + 1];
                    unsigned bl0 = blo[nt >> 1][(nt & 1) * 2];
                    unsigned bl1 = blo[nt >> 1][(nt & 1) * 2 + 1];
                    MMA16816(acc[mt][nt], ahi[mt], bh0, bh1);
                    MMA16816(acc[mt][nt], ahi[mt], bl0, bl1);
                    MMA16816(acc[mt][nt], alo[mt], bh0, bh1);
                }
        }
        __syncthreads();
    }

#pragma unroll
    for (int mt = 0; mt < 2; mt++) {
        int m0 = rowBase + wm + mt * 16 + (lane >> 2);
#pragma unroll
        for (int nt = 0; nt < 4; nt++) {
            int c = colBase + wn + nt * 8 + 2 * (lane & 3);
            float bb0 = g_bcat[c], bb1 = g_bcat[c + 1];
            float* p0 = g_Q + (size_t)m0 * LDQ + c;
            float* p1 = g_Q + (size_t)(m0 + 8) * LDQ + c;
            p0[0] = acc[mt][nt][0] + bb0; p0[1] = acc[mt][nt][1] + bb1;
            p1[0] = acc[mt][nt][2] + bb0; p1[1] = acc[mt][nt][3] + bb1;
        }
    }
}

// ---------------- comparator ----------------
__device__ __forceinline__ bool dless(float d1, int i1, float d2, int i2) {
    return (d1 < d2) || (d1 == d2 && i1 < i2);
}
__device__ __forceinline__ float warp_sort32(float m, int lane) {
#pragma unroll
    for (int k = 2; k <= 32; k <<= 1) {
#pragma unroll
        for (int j = k >> 1; j > 0; j >>= 1) {
            float other = __shfl_xor_sync(0xffffffffu, m, j);
            bool up = ((lane & k) == 0);
            bool lower = ((lane & j) == 0);
            float mn = fminf(m, other), mx = fmaxf(m, other);
            m = (lower == up) ? mn : mx;
        }
    }
    return m;
}

// ---------------- kNN ----------------
__global__ __launch_bounds__(256) void knn_kernel(const float* __restrict__ q_pos) {
    __shared__ float4 sP[N_];
    __shared__ float  sBd[8][CAP_];
    __shared__ int    sBi[8][CAP_];
    const int qbase = blockIdx.x * 8;
    const int b = qbase >> 11;
    const float* P = q_pos + (size_t)b * N_ * 3;
    for (int i = threadIdx.x; i < N_; i += 256) {
        float x = P[i * 3 + 0], y = P[i * 3 + 1], z = P[i * 3 + 2];
        sP[i] = make_float4(x, y, z, x * x + y * y + z * z);
    }
    __syncthreads();
    const int w = threadIdx.x >> 5, lane = threadIdx.x & 31;
    const float FINF = __int_as_float(0x7f800000);

    const int qi = qbase + w;
    const float4 Q = sP[qi & (N_ - 1)];

    float m = FINF;
    for (int t = 0; t < N_ / 32; t++) {
        float4 c = sP[t * 32 + lane];
        float dot = Q.x * c.x + Q.y * c.y + Q.z * c.z;
        float dd = fmaf(dot, -2.f, c.w + Q.w);
        m = fminf(m, dd);
    }
    float s = warp_sort32(m, lane);
    float T    = __shfl_sync(0xffffffffu, s, K_ - 1);
    float Tmax = __shfl_sync(0xffffffffu, s, 31);

    int cnt = 0;
    float Tuse = T;
    for (int attempt = 0; attempt < 2; attempt++) {
        cnt = 0;
        for (int t = 0; t < N_ / 32; t++) {
            int cand = t * 32 + lane;
            float4 c = sP[cand];
            float dot = Q.x * c.x + Q.y * c.y + Q.z * c.z;
            float dd = fmaf(dot, -2.f, c.w + Q.w);
            bool p = (dd <= Tuse);
            unsigned mask = __ballot_sync(0xffffffffu, p);
            if (p) {
                int pos = cnt + __popc(mask & ((1u << lane) - 1u));
                if (pos < CAP_) { sBd[w][pos] = dd; sBi[w][pos] = cand; }
            }
            cnt += __popc(mask);
        }
        if (cnt >= K_) break;
        Tuse = Tmax;
    }
    int n = cnt < CAP_ ? cnt : CAP_;
    __syncwarp();

    float mnx = FINF, mny = FINF, mnz = FINF;
    float mxx = -FINF, mxy = -FINF, mxz = -FINF;
    for (int r = 0; r < K_; r++) {
        float bd = FINF; int bi = 0x7fffffff;
        for (int i = lane; i < n; i += 32) {
            float dd = sBd[w][i]; int ii = sBi[w][i];
            if (dless(dd, ii, bd, bi)) { bd = dd; bi = ii; }
        }
#pragma unroll
        for (int off = 16; off; off >>= 1) {
            float od = __shfl_xor_sync(0xffffffffu, bd, off);
            int   oi = __shfl_xor_sync(0xffffffffu, bi, off);
            if (dless(od, oi, bd, bi)) { bd = od; bi = oi; }
        }
        if (lane == 0) g_knn[qi * K_ + r] = bi;
        float4 wp = sP[bi];
        mnx = fminf(mnx, wp.x); mxx = fmaxf(mxx, wp.x);
        mny = fminf(mny, wp.y); mxy = fmaxf(mxy, wp.y);
        mnz = fminf(mnz, wp.z); mxz = fmaxf(mxz, wp.z);
        for (int i = lane; i < n; i += 32)
            if (sBi[w][i] == bi) sBd[w][i] = FINF;
        __syncwarp();
    }
    if (lane == 0) {
        g_scale[qi * 3 + 0] = (mxx - mnx) * 0.5f;
        g_scale[qi * 3 + 1] = (mxy - mny) * 0.5f;
        g_scale[qi * 3 + 2] = (mxz - mnz) * 0.5f;
    }
}

// ---------------- per-point MLP ----------------
__global__ __launch_bounds__(256) void offset_kernel(
    const float* __restrict__ q_pos, const float* __restrict__ ln_g,
    const float* __restrict__ ln_b, const float* __restrict__ W2)
{
    const int w = threadIdx.x >> 5, lane = threadIdx.x & 31;
    const int p = blockIdx.x * 8 + w;
    const int b = p >> 11;
    const int c0 = lane * 12;

    float4 bq[3], lg[3], lb[3], w2f[9];
    const float* Bq = g_Q + (size_t)p * LDQ + C_ + c0;
#pragma unroll
    for (int t = 0; t < 3; t++) {
        bq[t] = *(const float4*)(Bq + t * 4);
        lg[t] = *(const float4*)(ln_g + c0 + t * 4);
        lb[t] = *(const float4*)(ln_b + c0 + t * 4);
    }
#pragma unroll
    for (int t = 0; t < 9; t++) w2f[t] = *(const float4*)(W2 + c0 * 3 + t * 4);
    const float* w2s = (const float*)w2f;
    const float* bqs = (const float*)bq;
    const float* lgs = (const float*)lg;
    const float* lbs = (const float*)lb;

    const float sx = g_scale[p * 3 + 0];
    const float sy = g_scale[p * 3 + 1];
    const float sz = g_scale[p * 3 + 2];

    for (int k = 0; k < K_; k++) {
        const int nb = g_knn[p * K_ + k];
        const int rownb = b * N_ + nb;
        const float* Arow = g_Q + (size_t)rownb * LDQ + c0;

        float h[12];
        float4 a0 = *(const float4*)(Arow);
        float4 a1 = *(const float4*)(Arow + 4);
        float4 a2 = *(const float4*)(Arow + 8);
        h[0] = a0.x + bqs[0]; h[1] = a0.y + bqs[1]; h[2] = a0.z + bqs[2]; h[3] = a0.w + bqs[3];
        h[4] = a1.x + bqs[4]; h[5] = a1.y + bqs[5]; h[6] = a1.z + bqs[6]; h[7] = a1.w + bqs[7];
        h[8] = a2.x + bqs[8]; h[9] = a2.y + bqs[9]; h[10]= a2.z + bqs[10];h[11]= a2.w + bqs[11];

        float s = 0.f;
#pragma unroll
        for (int j = 0; j < 12; j++) s += h[j];
#pragma unroll
        for (int off = 16; off; off >>= 1) s += __shfl_xor_sync(0xffffffffu, s, off);
        float mu = s * (1.f / C_);
        float v = 0.f;
#pragma unroll
        for (int j = 0; j < 12; j++) { float t = h[j] - mu; v += t * t; }
#pragma unroll
        for (int off = 16; off; off >>= 1) v += __shfl_xor_sync(0xffffffffu, v, off);
        float rstd = rsqrtf(v * (1.f / C_) + 1e-5f);

        float s0 = 0.f, s1 = 0.f, s2 = 0.f;
#pragma unroll
        for (int j = 0; j < 12; j++) {
            float g = (h[j] - mu) * rstd * lgs[j] + lbs[j];
            float y = 0.5f * g * (1.f + erff(g * 0.70710678118654752f));
            s0 = fmaf(y, w2s[j * 3 + 0], s0);
            s1 = fmaf(y, w2s[j * 3 + 1], s1);
            s2 = fmaf(y, w2s[j * 3 + 2], s2);
        }
#pragma unroll
        for (int off = 16; off; off >>= 1) {
            s0 += __shfl_xor_sync(0xffffffffu, s0, off);
            s1 += __shfl_xor_sync(0xffffffffu, s1, off);
            s2 += __shfl_xor_sync(0xffffffffu, s2, off);
        }
        if (lane == 0) {
            const int e = p * K_ + k;
            const float* pp = q_pos + (size_t)rownb * 3;
            g_shift[e * 3 + 0] = fmaf(tanhf(s0), sx, pp[0]);
            g_shift[e * 3 + 1] = fmaf(tanhf(s1), sy, pp[1]);
            g_shift[e * 3 + 2] = fmaf(tanhf(s2), sz, pp[2]);
        }
    }
}

// ---------------- three_nn ----------------
__global__ __launch_bounds__(256) void three_nn_kernel(const float* __restrict__ q_pos) {
    __shared__ float4 sP[N_];
    const int ebase = blockIdx.x * 64;
    const int b = ebase / (N_ * K_);
    const float* P = q_pos + (size_t)b * N_ * 3;
    for (int i = threadIdx.x; i < N_; i += 256) {
        float x = P[i * 3 + 0], y = P[i * 3 + 1], z = P[i * 3 + 2];
        sP[i] = make_float4(x, y, z, x * x + y * y + z * z);
    }
    __syncthreads();
    const int w = threadIdx.x >> 5, lane = threadIdx.x & 31;
    const float FINF = __int_as_float(0x7f800000);

    for (int sub = 0; sub < 8; sub++) {
        const int e = ebase + w * 8 + sub;
        const float px = g_shift[e * 3 + 0];
        const float py = g_shift[e * 3 + 1];
        const float pz = g_shift[e * 3 + 2];
        const float qw = px * px + py * py + pz * pz;

        float d0 = FINF, d1 = FINF, d2 = FINF;
        int   i0 = 0x7fffffff, i1 = 0x7fffffff, i2 = 0x7fffffff;
        for (int t = 0; t < N_ / 32; t++) {
            int cand = t * 32 + lane;
            float4 c = sP[cand];
            float dot = px * c.x + py * c.y + pz * c.z;
            float dd = fmaf(dot, -2.f, c.w + qw);
            if (dless(dd, cand, d2, i2)) {
                d2 = dd; i2 = cand;
                if (dless(d2, i2, d1, i1)) {
                    float td = d1; d1 = d2; d2 = td;
                    int ti = i1; i1 = i2; i2 = ti;
                    if (dless(d1, i1, d0, i0)) {
                        td = d0; d0 = d1; d1 = td;
                        ti = i0; i0 = i1; i1 = ti;
                    }
                }
            }
        }
        float rd[3]; int ri[3];
#pragma unroll
        for (int r = 0; r < 3; r++) {
            float bd = d0; int bi = i0;
#pragma unroll
            for (int off = 16; off; off >>= 1) {
                float od = __shfl_xor_sync(0xffffffffu, bd, off);
                int   oi = __shfl_xor_sync(0xffffffffu, bi, off);
                if (dless(od, oi, bd, bi)) { bd = od; bi = oi; }
            }
            rd[r] = bd; ri[r] = bi;
            if (i0 == bi) { d0 = d1; i0 = i1; d1 = d2; i1 = i2; d2 = FINF; i2 = 0x7fffffff; }
        }
        if (lane == 0) {
            float r0 = 1.f / (rd[0] + 1e-8f);
            float r1 = 1.f / (rd[1] + 1e-8f);
            float r2 = 1.f / (rd[2] + 1e-8f);
            float sm = r0 + r1 + r2;
            g_i3[e * 3 + 0] = ri[0]; g_w3[e * 3 + 0] = r0 / sm;
            g_i3[e * 3 + 1] = ri[1]; g_w3[e * 3 + 1] = r1 / sm;
            g_i3[e * 3 + 2] = ri[2]; g_w3[e * 3 + 2] = r2 / sm;
        }
    }
}

// ---------------- final ----------------
__global__ __launch_bounds__(96) void final_kernel(float* __restrict__ out) {
    const int row = blockIdx.x;
    const int b = row >> 11;
    const int tid = threadIdx.x;
    __shared__ int   sI[K_ * 3];
    __shared__ float sW[K_ * 3];
    const int e0 = row * K_;
    if (tid < K_ * 3) { sI[tid] = g_i3[e0 * 3 + tid]; sW[tid] = g_w3[e0 * 3 + tid]; }
    __syncthreads();

    const size_t baseB = (size_t)b * N_ * LDQ;
    float4 qp = *(const float4*)(g_Q + (size_t)row * LDQ + 3 * C_ + tid * 4);
    const float NINF = __int_as_float(0xff800000);
    float4 mx = make_float4(NINF, NINF, NINF, NINF);

    for (int k = 0; k < K_; k++) {
        int   a0 = sI[3 * k + 0], a1 = sI[3 * k + 1], a2 = sI[3 * k + 2];
        float w0 = sW[3 * k + 0], w1 = sW[3 * k + 1], w2 = sW[3 * k + 2];
        float4 r0 = *(const float4*)(g_Q + baseB + (size_t)a0 * LDQ + 2 * C_ + tid * 4);
        float4 r1 = *(const float4*)(g_Q + baseB + (size_t)a1 * LDQ + 2 * C_ + tid * 4);
        float4 r2 = *(const float4*)(g_Q + baseB + (size_t)a2 * LDQ + 2 * C_ + tid * 4);
        float v0 = qp.x + w0 * r0.x + w1 * r1.x + w2 * r2.x;
        float v1 = qp.y + w0 * r0.y + w1 * r1.y + w2 * r2.y;
        float v2 = qp.z + w0 * r0.z + w1 * r1.z + w2 * r2.z;
        float v3 = qp.w + w0 * r0.w + w1 * r1.w + w2 * r2.w;
        v0 = v0 > 0.f ? v0 : 0.2f * v0;
        v1 = v1 > 0.f ? v1 : 0.2f * v1;
        v2 = v2 > 0.f ? v2 : 0.2f * v2;
        v3 = v3 > 0.f ? v3 : 0.2f * v3;
        mx.x = fmaxf(mx.x, v0); mx.y = fmaxf(mx.y, v1);
        mx.z = fmaxf(mx.z, v2); mx.w = fmaxf(mx.w, v3);
    }
    *(float4*)(out + (size_t)row * C_ + tid * 4) = mx;
}

// ---------------- launch ----------------
extern "C" void kernel_launch(void* const* d_in, const int* in_sizes, int n_in,
                              void* d_out, int out_size) {
    const float* q     = (const float*)d_in[0];
    const float* q_pos = (const float*)d_in[1];
    const float* Wv    = (const float*)d_in[2];
    const float* bv    = (const float*)d_in[3];
    const float* W1    = (const float*)d_in[4];
    const float* b1    = (const float*)d_in[5];
    const float* ln_g  = (const float*)d_in[6];
    const float* ln_b  = (const float*)d_in[7];
    const float* W2    = (const float*)d_in[8];
    const float* Wk    = (const float*)d_in[9];
    const float* bk    = (const float*)d_in[10];

    cudaFuncSetAttribute(gemm_mma, cudaFuncAttributeMaxDynamicSharedMemorySize, G_TOT);

    prep_wbig<<<(C_ * (LDQ - C_) + 255) / 256, 256>>>(W1, Wk);
    prep_bias<<<48 + (LDQ - C_ + 255) / 256, 256>>>(bv, W1, b1, bk);
    // W_A = Wv @ W1_top -> g_Wbig cols [0,384)
    sgemm128<<<dim3(C_ / 128, C_ / 128), 256>>>(Wv, W1, F_DST_WBIG,
                                                C_, C_, C_, C_, C_, LDQ);
    conv_w<<<(C_ * LDQ) / 256, 256>>>();
    conv_q<<<(ROWS_ * C_) / 256, 256>>>(q);
    knn_kernel<<<ROWS_ / 8, 256>>>(q_pos);
    // g_Q = q @ Wbig + bcat  (split-bf16 mma.sync, cp.async pipelined)
    gemm_mma<<<dim3(LDQ / 64, ROWS_ / 128), 256, G_TOT>>>();
    offset_kernel<<<ROWS_ / 8, 256>>>(q_pos, ln_g, ln_b, W2);
    three_nn_kernel<<<EDGES_ / 64, 256>>>(q_pos);
    final_kernel<<<ROWS_, 96>>>((float*)d_out);
}

// round 12
// speedup vs baseline: 1.7507x; 1.2098x over previous
#include <cuda_runtime.h>
#include <cuda_bf16.h>
#include <math.h>

#define B_ 4
#define N_ 2048
#define C_ 384
#define K_ 10
#define ROWS_ (B_*N_)      // 8192
#define EDGES_ (ROWS_*K_)  // 81920
#define LDQ 1536
#define CAP_ 224

// ---------------- scratch ----------------
__device__ float g_Q[ROWS_*LDQ];
__device__ float g_Wbig[C_*LDQ];            // fp32 [k][n]
__device__ float g_bcat[LDQ];
__device__ __nv_bfloat16 g_qhi[ROWS_*C_];   // q split, [M,K]
__device__ __nv_bfloat16 g_qlo[ROWS_*C_];
__device__ __nv_bfloat16 g_wbhi[C_*LDQ];    // Wbig split, [K,N]
__device__ __nv_bfloat16 g_wblo[C_*LDQ];
__device__ int   g_knn[ROWS_*K_];
__device__ float g_scale[ROWS_*3];
__device__ float g_shift[EDGES_*3];
__device__ int   g_i3[EDGES_*3];
__device__ float g_w3[EDGES_*3];

#define F_DST_WBIG 2

// ---------------- weight prep ----------------
__global__ void prep_wbig(const float* __restrict__ W1, const float* __restrict__ Wk) {
    int i = blockIdx.x * 256 + threadIdx.x;
    if (i >= C_ * (LDQ - C_)) return;
    int r = i / (LDQ - C_), c = i % (LDQ - C_);
    float v;
    if (c < C_)            v = W1[(C_ + r) * C_ + c];
    else if (c < 2 * C_)   v = Wk[r * C_ + (c - C_)];
    else                   v = Wk[(C_ + r) * C_ + (c - 2*C_)] - Wk[r * C_ + (c - 2*C_)];
    g_Wbig[r * LDQ + C_ + c] = v;
}

__global__ __launch_bounds__(256) void prep_bias(
    const float* __restrict__ bv, const float* __restrict__ W1,
    const float* __restrict__ b1, const float* __restrict__ bk)
{
    if (blockIdx.x < 48) {
        int w = threadIdx.x >> 5, lane = threadIdx.x & 31;
        int o = blockIdx.x * 8 + w;
        float s = 0.f;
        for (int t = 0; t < 12; t++) {
            int j = t * 32 + lane;
            s = fmaf(bv[j], W1[j * C_ + o], s);
        }
#pragma unroll
        for (int off = 16; off; off >>= 1) s += __shfl_xor_sync(0xffffffffu, s, off);
        if (lane == 0) g_bcat[o] = s;
    } else {
        int i = (blockIdx.x - 48) * 256 + threadIdx.x;
        if (i >= LDQ - C_) return;
        float v;
        if (i < C_)            v = b1[i];
        else if (i < 2 * C_)   v = 0.f;
        else                   v = bk[i - 2 * C_];
        g_bcat[C_ + i] = v;
    }
}

// ---------------- split conversions ----------------
__global__ void conv_q(const float* __restrict__ q) {
    int i = blockIdx.x * 256 + threadIdx.x;
    float x = q[i];
    __nv_bfloat16 h = __float2bfloat16(x);
    g_qhi[i] = h;
    g_qlo[i] = __float2bfloat16(x - __bfloat162float(h));
}

__global__ void conv_w() {
    int i = blockIdx.x * 256 + threadIdx.x;
    float x = g_Wbig[i];
    __nv_bfloat16 h = __float2bfloat16(x);
    g_wbhi[i] = h;
    g_wblo[i] = __float2bfloat16(x - __bfloat162float(h));
}

// ---------------- small fp32 SGEMM (W_A = Wv @ W1_top) ----------------
__global__ __launch_bounds__(256) void sgemm128(
    const float* __restrict__ Aex, const float* __restrict__ Bex,
    int flags, int M, int N, int K, int ldA, int ldB, int ldC)
{
    const float* A  = Aex;
    const float* Bm = Bex;
    float* Cm       = (flags & F_DST_WBIG) ? g_Wbig : g_Q;

    __shared__ float As[2][8][132];
    __shared__ float Bs[2][8][128];

    const int tid = threadIdx.x;
    const int tx = tid & 15;
    const int ty = tid >> 4;
    const int rowBase = blockIdx.y * 128;
    const int colBase = blockIdx.x * 128;

    const int arow = tid >> 1, acol = (tid & 1) * 4;
    const int brow = tid >> 5, bcol = (tid & 31) * 4;

    const float* Aptr = A + (size_t)(rowBase + arow) * ldA + acol;
    const float* Bptr = Bm + (size_t)brow * ldB + colBase + bcol;

    float4 aReg = *(const float4*)Aptr;
    float4 bReg = *(const float4*)Bptr;

    float acc[8][8];
#pragma unroll
    for (int i = 0; i < 8; i++)
#pragma unroll
        for (int j = 0; j < 8; j++) acc[i][j] = 0.f;

    As[0][acol + 0][arow] = aReg.x; As[0][acol + 1][arow] = aReg.y;
    As[0][acol + 2][arow] = aReg.z; As[0][acol + 3][arow] = aReg.w;
    *(float4*)&Bs[0][brow][bcol] = bReg;
    __syncthreads();

    const int nIter = K >> 3;
    int buf = 0;
    for (int it = 0; it < nIter; it++) {
        if (it + 1 < nIter) {
            aReg = *(const float4*)(Aptr + (it + 1) * 8);
            bReg = *(const float4*)(Bptr + (size_t)(it + 1) * 8 * ldB);
        }
#pragma unroll
        for (int kk = 0; kk < 8; kk++) {
            float4 a0 = *(const float4*)&As[buf][kk][ty * 4];
            float4 a1 = *(const float4*)&As[buf][kk][64 + ty * 4];
            float4 b0 = *(const float4*)&Bs[buf][kk][tx * 4];
            float4 b1 = *(const float4*)&Bs[buf][kk][64 + tx * 4];
            float am[8] = {a0.x, a0.y, a0.z, a0.w, a1.x, a1.y, a1.z, a1.w};
            float bn[8] = {b0.x, b0.y, b0.z, b0.w, b1.x, b1.y, b1.z, b1.w};
#pragma unroll
            for (int i = 0; i < 8; i++)
#pragma unroll
                for (int j = 0; j < 8; j++)
                    acc[i][j] = fmaf(am[i], bn[j], acc[i][j]);
        }
        if (it + 1 < nIter) {
            int nb = buf ^ 1;
            As[nb][acol + 0][arow] = aReg.x; As[nb][acol + 1][arow] = aReg.y;
            As[nb][acol + 2][arow] = aReg.z; As[nb][acol + 3][arow] = aReg.w;
            *(float4*)&Bs[nb][brow][bcol] = bReg;
            __syncthreads();
            buf = nb;
        }
    }
#pragma unroll
    for (int i = 0; i < 8; i++) {
        int r = rowBase + ((i < 4) ? (ty * 4 + i) : (64 + ty * 4 + i - 4));
        float* crow = Cm + (size_t)r * ldC + colBase;
        *(float4*)(crow + tx * 4) =
            make_float4(acc[i][0], acc[i][1], acc[i][2], acc[i][3]);
        *(float4*)(crow + 64 + tx * 4) =
            make_float4(acc[i][4], acc[i][5], acc[i][6], acc[i][7]);
    }
}

// ================= mma.sync split-bf16 GEMM, cp.async double-buffered =============
#define GA_HI 0
#define GA_LO 18432
#define GB_HI 36864
#define GB_LO 46080
#define G_STG 55296
#define G_TOT (2*G_STG)     // 110592

__device__ __forceinline__ unsigned smem_u32(const void* p) {
    unsigned a;
    asm("{ .reg .u64 t; cvta.to.shared.u64 t, %1; cvt.u32.u64 %0, t; }" : "=r"(a) : "l"(p));
    return a;
}
#define CP16(dst, src) \
    asm volatile("cp.async.cg.shared.global [%0], [%1], 16;" :: "r"(dst), "l"(src))
#define CP_COMMIT() asm volatile("cp.async.commit_group;" ::: "memory")
#define CP_WAIT0()  asm volatile("cp.async.wait_group 0;" ::: "memory")
#define CP_WAIT1()  asm volatile("cp.async.wait_group 1;" ::: "memory")
#define LDSM4(rg, addr) \
    asm volatile("ldmatrix.sync.aligned.m8n8.x4.shared.b16 {%0,%1,%2,%3}, [%4];" \
        : "=r"((rg)[0]), "=r"((rg)[1]), "=r"((rg)[2]), "=r"((rg)[3]) : "r"(addr))
#define LDSM4T(rg, addr) \
    asm volatile("ldmatrix.sync.aligned.m8n8.x4.trans.shared.b16 {%0,%1,%2,%3}, [%4];" \
        : "=r"((rg)[0]), "=r"((rg)[1]), "=r"((rg)[2]), "=r"((rg)[3]) : "r"(addr))
#define MMA16816(d, a, b0, b1) \
    asm volatile("mma.sync.aligned.m16n8k16.row.col.f32.bf16.bf16.f32 " \
        "{%0,%1,%2,%3}, {%4,%5,%6,%7}, {%8,%9}, {%0,%1,%2,%3};" \
        : "+f"((d)[0]), "+f"((d)[1]), "+f"((d)[2]), "+f"((d)[3]) \
        : "r"((a)[0]), "r"((a)[1]), "r"((a)[2]), "r"((a)[3]), "r"(b0), "r"(b1))

__device__ __forceinline__ void gemm_load_stage(
    unsigned base, int kc, int rowBase, int colBase, int tid)
{
#pragma unroll
    for (int t = 0; t < 4; t++) {
        int i = tid + t * 256;
        int r = i >> 3, c = i & 7;
        unsigned off = r * 144 + c * 16;
        size_t g = (size_t)(rowBase + r) * C_ + kc * 64 + c * 8;
        CP16(base + GA_HI + off, (const void*)(g_qhi + g));
        CP16(base + GA_LO + off, (const void*)(g_qlo + g));
    }
#pragma unroll
    for (int t = 0; t < 2; t++) {
        int i = tid + t * 256;
        int r = i >> 3, c = i & 7;
        unsigned off = r * 144 + c * 16;
        size_t g = (size_t)(kc * 64 + r) * LDQ + colBase + c * 8;
        CP16(base + GB_HI + off, (const void*)(g_wbhi + g));
        CP16(base + GB_LO + off, (const void*)(g_wblo + g));
    }
}

__global__ __launch_bounds__(256) void gemm_mma() {
    extern __shared__ char sm[];
    const unsigned sb = smem_u32(sm);
    const int tid = threadIdx.x;
    const int w = tid >> 5, lane = tid & 31;
    const int rowBase = blockIdx.y * 128;
    const int colBase = blockIdx.x * 64;
    const int wm = (w & 3) * 32;
    const int wn = (w >> 2) * 32;

    float acc[2][4][4];
#pragma unroll
    for (int mt = 0; mt < 2; mt++)
#pragma unroll
        for (int nt = 0; nt < 4; nt++)
#pragma unroll
            for (int j = 0; j < 4; j++) acc[mt][nt][j] = 0.f;

    const unsigned aRow = (lane & 15);
    const unsigned aKb  = (lane >> 4) << 4;
    const unsigned bK   = (lane & 7) + ((lane >> 3) & 1) * 8;
    const unsigned bN   = ((lane >> 4) & 1) * 8;

    gemm_load_stage(sb, 0, rowBase, colBase, tid);
    CP_COMMIT();

    for (int kc = 0; kc < 6; kc++) {
        const unsigned buf = sb + (kc & 1) * G_STG;
        if (kc + 1 < 6) {
            gemm_load_stage(sb + ((kc + 1) & 1) * G_STG, kc + 1, rowBase, colBase, tid);
            CP_COMMIT();
            CP_WAIT1();
        } else {
            CP_WAIT0();
        }
        __syncthreads();

#pragma unroll
        for (int ks = 0; ks < 4; ks++) {
            unsigned ahi[2][4], alo[2][4], bhi[2][4], blo[2][4];
#pragma unroll
            for (int mt = 0; mt < 2; mt++) {
                unsigned addr = buf + GA_HI + (wm + mt * 16 + aRow) * 144 + ks * 32 + aKb;
                LDSM4(ahi[mt], addr);
                LDSM4(alo[mt], addr + (GA_LO - GA_HI));
            }
#pragma unroll
            for (int ng = 0; ng < 2; ng++) {
                unsigned addr = buf + GB_HI + (ks * 16 + bK) * 144 + (wn + ng * 16 + bN) * 2;
                LDSM4T(bhi[ng], addr);
                LDSM4T(blo[ng], addr + (GB_LO - GB_HI));
            }
#pragma unroll
            for (int mt = 0; mt < 2; mt++)
#pragma unroll
                for (int nt = 0; nt < 4; nt++) {
                    unsigned bh0 = bhi[nt >> 1][(nt & 1) * 2];
                    unsigned bh1 = bhi[nt >> 1][(nt & 1) * 2 + 1];
                    unsigned bl0 = blo[nt >> 1][(nt & 1) * 2];
                    unsigned bl1 = blo[nt >> 1][(nt & 1) * 2 + 1];
                    MMA16816(acc[mt][nt], ahi[mt], bh0, bh1);
                    MMA16816(acc[mt][nt], ahi[mt], bl0, bl1);
                    MMA16816(acc[mt][nt], alo[mt], bh0, bh1);
                }
        }
        __syncthreads();
    }

#pragma unroll
    for (int mt = 0; mt < 2; mt++) {
        int m0 = rowBase + wm + mt * 16 + (lane >> 2);
#pragma unroll
        for (int nt = 0; nt < 4; nt++) {
            int c = colBase + wn + nt * 8 + 2 * (lane & 3);
            float bb0 = g_bcat[c], bb1 = g_bcat[c + 1];
            float* p0 = g_Q + (size_t)m0 * LDQ + c;
            float* p1 = g_Q + (size_t)(m0 + 8) * LDQ + c;
            p0[0] = acc[mt][nt][0] + bb0; p0[1] = acc[mt][nt][1] + bb1;
            p1[0] = acc[mt][nt][2] + bb0; p1[1] = acc[mt][nt][3] + bb1;
        }
    }
}

// ---------------- comparator ----------------
__device__ __forceinline__ bool dless(float d1, int i1, float d2, int i2) {
    return (d1 < d2) || (d1 == d2 && i1 < i2);
}
__device__ __forceinline__ float warp_sort32(float m, int lane) {
#pragma unroll
    for (int k = 2; k <= 32; k <<= 1) {
#pragma unroll
        for (int j = k >> 1; j > 0; j >>= 1) {
            float other = __shfl_xor_sync(0xffffffffu, m, j);
            bool up = ((lane & k) == 0);
            bool lower = ((lane & j) == 0);
            float mn = fminf(m, other), mx = fmaxf(m, other);
            m = (lower == up) ? mn : mx;
        }
    }
    return m;
}

// ---------------- kNN ----------------
__global__ __launch_bounds__(256) void knn_kernel(const float* __restrict__ q_pos) {
    __shared__ float4 sP[N_];
    __shared__ float  sBd[8][CAP_];
    __shared__ int    sBi[8][CAP_];
    const int qbase = blockIdx.x * 8;
    const int b = qbase >> 11;
    const float* P = q_pos + (size_t)b * N_ * 3;
    for (int i = threadIdx.x; i < N_; i += 256) {
        float x = P[i * 3 + 0], y = P[i * 3 + 1], z = P[i * 3 + 2];
        sP[i] = make_float4(x, y, z, x * x + y * y + z * z);
    }
    __syncthreads();
    const int w = threadIdx.x >> 5, lane = threadIdx.x & 31;
    const float FINF = __int_as_float(0x7f800000);

    const int qi = qbase + w;
    const float4 Q = sP[qi & (N_ - 1)];

    float m = FINF;
    for (int t = 0; t < N_ / 32; t++) {
        float4 c = sP[t * 32 + lane];
        float dot = Q.x * c.x + Q.y * c.y + Q.z * c.z;
        float dd = fmaf(dot, -2.f, c.w + Q.w);
        m = fminf(m, dd);
    }
    float s = warp_sort32(m, lane);
    float T    = __shfl_sync(0xffffffffu, s, K_ - 1);
    float Tmax = __shfl_sync(0xffffffffu, s, 31);

    int cnt = 0;
    float Tuse = T;
    for (int attempt = 0; attempt < 2; attempt++) {
        cnt = 0;
        for (int t = 0; t < N_ / 32; t++) {
            int cand = t * 32 + lane;
            float4 c = sP[cand];
            float dot = Q.x * c.x + Q.y * c.y + Q.z * c.z;
            float dd = fmaf(dot, -2.f, c.w + Q.w);
            bool p = (dd <= Tuse);
            unsigned mask = __ballot_sync(0xffffffffu, p);
            if (p) {
                int pos = cnt + __popc(mask & ((1u << lane) - 1u));
                if (pos < CAP_) { sBd[w][pos] = dd; sBi[w][pos] = cand; }
            }
            cnt += __popc(mask);
        }
        if (cnt >= K_) break;
        Tuse = Tmax;
    }
    int n = cnt < CAP_ ? cnt : CAP_;
    __syncwarp();

    float mnx = FINF, mny = FINF, mnz = FINF;
    float mxx = -FINF, mxy = -FINF, mxz = -FINF;
    for (int r = 0; r < K_; r++) {
        float bd = FINF; int bi = 0x7fffffff;
        for (int i = lane; i < n; i += 32) {
            float dd = sBd[w][i]; int ii = sBi[w][i];
            if (dless(dd, ii, bd, bi)) { bd = dd; bi = ii; }
        }
#pragma unroll
        for (int off = 16; off; off >>= 1) {
            float od = __shfl_xor_sync(0xffffffffu, bd, off);
            int   oi = __shfl_xor_sync(0xffffffffu, bi, off);
            if (dless(od, oi, bd, bi)) { bd = od; bi = oi; }
        }
        if (lane == 0) g_knn[qi * K_ + r] = bi;
        float4 wp = sP[bi];
        mnx = fminf(mnx, wp.x); mxx = fmaxf(mxx, wp.x);
        mny = fminf(mny, wp.y); mxy = fmaxf(mxy, wp.y);
        mnz = fminf(mnz, wp.z); mxz = fmaxf(mxz, wp.z);
        for (int i = lane; i < n; i += 32)
            if (sBi[w][i] == bi) sBd[w][i] = FINF;
        __syncwarp();
    }
    if (lane == 0) {
        g_scale[qi * 3 + 0] = (mxx - mnx) * 0.5f;
        g_scale[qi * 3 + 1] = (mxy - mny) * 0.5f;
        g_scale[qi * 3 + 2] = (mxz - mnz) * 0.5f;
    }
}

// ---------------- per-point MLP ----------------
__global__ __launch_bounds__(256) void offset_kernel(
    const float* __restrict__ q_pos, const float* __restrict__ ln_g,
    const float* __restrict__ ln_b, const float* __restrict__ W2)
{
    const int w = threadIdx.x >> 5, lane = threadIdx.x & 31;
    const int p = blockIdx.x * 8 + w;
    const int b = p >> 11;
    const int c0 = lane * 12;

    float4 bq[3], lg[3], lb[3], w2f[9];
    const float* Bq = g_Q + (size_t)p * LDQ + C_ + c0;
#pragma unroll
    for (int t = 0; t < 3; t++) {
        bq[t] = *(const float4*)(Bq + t * 4);
        lg[t] = *(const float4*)(ln_g + c0 + t * 4);
        lb[t] = *(const float4*)(ln_b + c0 + t * 4);
    }
#pragma unroll
    for (int t = 0; t < 9; t++) w2f[t] = *(const float4*)(W2 + c0 * 3 + t * 4);
    const float* w2s = (const float*)w2f;
    const float* bqs = (const float*)bq;
    const float* lgs = (const float*)lg;
    const float* lbs = (const float*)lb;

    const float sx = g_scale[p * 3 + 0];
    const float sy = g_scale[p * 3 + 1];
    const float sz = g_scale[p * 3 + 2];

    for (int k = 0; k < K_; k++) {
        const int nb = g_knn[p * K_ + k];
        const int rownb = b * N_ + nb;
        const float* Arow = g_Q + (size_t)rownb * LDQ + c0;

        float h[12];
        float4 a0 = *(const float4*)(Arow);
        float4 a1 = *(const float4*)(Arow + 4);
        float4 a2 = *(const float4*)(Arow + 8);
        h[0] = a0.x + bqs[0]; h[1] = a0.y + bqs[1]; h[2] = a0.z + bqs[2]; h[3] = a0.w + bqs[3];
        h[4] = a1.x + bqs[4]; h[5] = a1.y + bqs[5]; h[6] = a1.z + bqs[6]; h[7] = a1.w + bqs[7];
        h[8] = a2.x + bqs[8]; h[9] = a2.y + bqs[9]; h[10]= a2.z + bqs[10];h[11]= a2.w + bqs[11];

        float s = 0.f;
#pragma unroll
        for (int j = 0; j < 12; j++) s += h[j];
#pragma unroll
        for (int off = 16; off; off >>= 1) s += __shfl_xor_sync(0xffffffffu, s, off);
        float mu = s * (1.f / C_);
        float v = 0.f;
#pragma unroll
        for (int j = 0; j < 12; j++) { float t = h[j] - mu; v += t * t; }
#pragma unroll
        for (int off = 16; off; off >>= 1) v += __shfl_xor_sync(0xffffffffu, v, off);
        float rstd = rsqrtf(v * (1.f / C_) + 1e-5f);

        float s0 = 0.f, s1 = 0.f, s2 = 0.f;
#pragma unroll
        for (int j = 0; j < 12; j++) {
            float g = (h[j] - mu) * rstd * lgs[j] + lbs[j];
            float y = 0.5f * g * (1.f + erff(g * 0.70710678118654752f));
            s0 = fmaf(y, w2s[j * 3 + 0], s0);
            s1 = fmaf(y, w2s[j * 3 + 1], s1);
            s2 = fmaf(y, w2s[j * 3 + 2], s2);
        }
#pragma unroll
        for (int off = 16; off; off >>= 1) {
            s0 += __shfl_xor_sync(0xffffffffu, s0, off);
            s1 += __shfl_xor_sync(0xffffffffu, s1, off);
            s2 += __shfl_xor_sync(0xffffffffu, s2, off);
        }
        if (lane == 0) {
            const int e = p * K_ + k;
            const float* pp = q_pos + (size_t)rownb * 3;
            g_shift[e * 3 + 0] = fmaf(tanhf(s0), sx, pp[0]);
            g_shift[e * 3 + 1] = fmaf(tanhf(s1), sy, pp[1]);
            g_shift[e * 3 + 2] = fmaf(tanhf(s2), sz, pp[2]);
        }
    }
}

// ---------------- three_nn: 4 edges per scan pass, shifted-threshold top-3 ---------
__global__ __launch_bounds__(256) void three_nn_kernel(const float* __restrict__ q_pos) {
    __shared__ float4 sP[N_];
    const int ebase = blockIdx.x * 64;
    const int b = ebase / (N_ * K_);
    const float* P = q_pos + (size_t)b * N_ * 3;
    for (int i = threadIdx.x; i < N_; i += 256) {
        float x = P[i * 3 + 0], y = P[i * 3 + 1], z = P[i * 3 + 2];
        sP[i] = make_float4(x, y, z, x * x + y * y + z * z);
    }
    __syncthreads();
    const int w = threadIdx.x >> 5, lane = threadIdx.x & 31;
    const float FINF = __int_as_float(0x7f800000);

    for (int g = 0; g < 2; g++) {
        const int e0 = ebase + w * 8 + g * 4;
        float px[4], py[4], pz[4], qw[4];
#pragma unroll
        for (int j = 0; j < 4; j++) {
            px[j] = g_shift[(e0 + j) * 3 + 0];
            py[j] = g_shift[(e0 + j) * 3 + 1];
            pz[j] = g_shift[(e0 + j) * 3 + 2];
            qw[j] = px[j] * px[j] + py[j] * py[j] + pz[j] * pz[j];
        }
        // shifted-threshold top-3 per edge: track dp = -2*dot + c.w  (= dd - qw)
        float d0[4], d1[4], d2[4];
        int   i0[4], i1[4], i2[4];
#pragma unroll
        for (int j = 0; j < 4; j++) {
            d0[j] = d1[j] = d2[j] = FINF;
            i0[j] = i1[j] = i2[j] = 0x7fffffff;
        }

        for (int t = 0; t < N_ / 32; t++) {
            int cand = t * 32 + lane;
            float4 c = sP[cand];
#pragma unroll
            for (int j = 0; j < 4; j++) {
                float dot = px[j] * c.x + py[j] * c.y + pz[j] * c.z;
                float dp = fmaf(dot, -2.f, c.w);
                // strict < : in-lane candidates arrive in increasing index, so
                // keep-on-equal preserves lowest-index-wins exactly.
                if (dp < d2[j]) {
                    if (dp < d1[j]) {
                        d2[j] = d1[j]; i2[j] = i1[j];
                        if (dp < d0[j]) {
                            d1[j] = d0[j]; i1[j] = i0[j];
                            d0[j] = dp;    i0[j] = cand;
                        } else {
                            d1[j] = dp;    i1[j] = cand;
                        }
                    } else {
                        d2[j] = dp; i2[j] = cand;
                    }
                }
            }
        }

#pragma unroll
        for (int j = 0; j < 4; j++) {
            float rd[3]; int ri[3];
            float a0 = d0[j], a1 = d1[j], a2 = d2[j];
            int   b0 = i0[j], b1 = i1[j], b2 = i2[j];
#pragma unroll
            for (int r = 0; r < 3; r++) {
                float bd = a0; int bi = b0;
#pragma unroll
                for (int off = 16; off; off >>= 1) {
                    float od = __shfl_xor_sync(0xffffffffu, bd, off);
                    int   oi = __shfl_xor_sync(0xffffffffu, bi, off);
                    if (dless(od, oi, bd, bi)) { bd = od; bi = oi; }
                }
                rd[r] = bd; ri[r] = bi;
                if (b0 == bi) { a0 = a1; b0 = b1; a1 = a2; b1 = b2;
                                a2 = FINF; b2 = 0x7fffffff; }
            }
            if (lane == 0) {
                const int e = e0 + j;
                float r0 = 1.f / (rd[0] + qw[j] + 1e-8f);
                float r1 = 1.f / (rd[1] + qw[j] + 1e-8f);
                float r2 = 1.f / (rd[2] + qw[j] + 1e-8f);
                float sm = r0 + r1 + r2;
                g_i3[e * 3 + 0] = ri[0]; g_w3[e * 3 + 0] = r0 / sm;
                g_i3[e * 3 + 1] = ri[1]; g_w3[e * 3 + 1] = r1 / sm;
                g_i3[e * 3 + 2] = ri[2]; g_w3[e * 3 + 2] = r2 / sm;
            }
        }
    }
}

// ---------------- final ----------------
__global__ __launch_bounds__(96) void final_kernel(float* __restrict__ out) {
    const int row = blockIdx.x;
    const int b = row >> 11;
    const int tid = threadIdx.x;
    __shared__ int   sI[K_ * 3];
    __shared__ float sW[K_ * 3];
    const int e0 = row * K_;
    if (tid < K_ * 3) { sI[tid] = g_i3[e0 * 3 + tid]; sW[tid] = g_w3[e0 * 3 + tid]; }
    __syncthreads();

    const size_t baseB = (size_t)b * N_ * LDQ;
    float4 qp = *(const float4*)(g_Q + (size_t)row * LDQ + 3 * C_ + tid * 4);
    const float NINF = __int_as_float(0xff800000);
    float4 mx = make_float4(NINF, NINF, NINF, NINF);

    for (int k = 0; k < K_; k++) {
        int   a0 = sI[3 * k + 0], a1 = sI[3 * k + 1], a2 = sI[3 * k + 2];
        float w0 = sW[3 * k + 0], w1 = sW[3 * k + 1], w2 = sW[3 * k + 2];
        float4 r0 = *(const float4*)(g_Q + baseB + (size_t)a0 * LDQ + 2 * C_ + tid * 4);
        float4 r1 = *(const float4*)(g_Q + baseB + (size_t)a1 * LDQ + 2 * C_ + tid * 4);
        float4 r2 = *(const float4*)(g_Q + baseB + (size_t)a2 * LDQ + 2 * C_ + tid * 4);
        float v0 = qp.x + w0 * r0.x + w1 * r1.x + w2 * r2.x;
        float v1 = qp.y + w0 * r0.y + w1 * r1.y + w2 * r2.y;
        float v2 = qp.z + w0 * r0.z + w1 * r1.z + w2 * r2.z;
        float v3 = qp.w + w0 * r0.w + w1 * r1.w + w2 * r2.w;
        v0 = v0 > 0.f ? v0 : 0.2f * v0;
        v1 = v1 > 0.f ? v1 : 0.2f * v1;
        v2 = v2 > 0.f ? v2 : 0.2f * v2;
        v3 = v3 > 0.f ? v3 : 0.2f * v3;
        mx.x = fmaxf(mx.x, v0); mx.y = fmaxf(mx.y, v1);
        mx.z = fmaxf(mx.z, v2); mx.w = fmaxf(mx.w, v3);
    }
    *(float4*)(out + (size_t)row * C_ + tid * 4) = mx;
}

// ---------------- launch ----------------
extern "C" void kernel_launch(void* const* d_in, const int* in_sizes, int n_in,
                              void* d_out, int out_size) {
    const float* q     = (const float*)d_in[0];
    const float* q_pos = (const float*)d_in[1];
    const float* Wv    = (const float*)d_in[2];
    const float* bv    = (const float*)d_in[3];
    const float* W1    = (const float*)d_in[4];
    const float* b1    = (const float*)d_in[5];
    const float* ln_g  = (const float*)d_in[6];
    const float* ln_b  = (const float*)d_in[7];
    const float* W2    = (const float*)d_in[8];
    const float* Wk    = (const float*)d_in[9];
    const float* bk    = (const float*)d_in[10];

    cudaFuncSetAttribute(gemm_mma, cudaFuncAttributeMaxDynamicSharedMemorySize, G_TOT);

    prep_wbig<<<(C_ * (LDQ - C_) + 255) / 256, 256>>>(W1, Wk);
    prep_bias<<<48 + (LDQ - C_ + 255) / 256, 256>>>(bv, W1, b1, bk);
    sgemm128<<<dim3(C_ / 128, C_ / 128), 256>>>(Wv, W1, F_DST_WBIG,
                                                C_, C_, C_, C_, C_, LDQ);
    conv_w<<<(C_ * LDQ) / 256, 256>>>();
    conv_q<<<(ROWS_ * C_) / 256, 256>>>(q);
    knn_kernel<<<ROWS_ / 8, 256>>>(q_pos);
    gemm_mma<<<dim3(LDQ / 64, ROWS_ / 128), 256, G_TOT>>>();
    offset_kernel<<<ROWS_ / 8, 256>>>(q_pos, ln_g, ln_b, W2);
    three_nn_kernel<<<EDGES_ / 64, 256>>>(q_pos);
    final_kernel<<<ROWS_, 96>>>((float*)d_out);
}